// round 7
// baseline (speedup 1.0000x reference)
#include <cuda_runtime.h>
#include <cuda_bf16.h>
#include <math.h>
#include <stdint.h>

#define Nn 64
#define Tt 512
#define Dd 1024
#define Hh 1024
#define G4 4096   // 4*Hh
#define KSPL 4
#define KPER 256  // Hh / KSPL
#define NBLK 128  // persistent grid (co-resident on 148 SMs)

// ---------------- packed fp32 FMA for the xW GEMM ----------------
#define FMA2(d, a, b) asm("fma.rn.f32x2 %0, %1, %2, %0;" : "+l"(d) : "l"(a), "l"(b))
union F2U { unsigned long long u; float2 f; };

// ---------------- device scratch (allocation-free rule) ----------------
__device__ float g_xw[(size_t)Nn * Tt * G4];      // input projection [N*T,4H]
__device__ float g_c[Nn * Hh];                    // cell state
__device__ float g_p[KSPL][Nn][G4];               // K-split partials of h@Wh
__device__ __nv_bfloat16 g_whT_h[(size_t)G4 * Hh];// Wh^T hi  [4096 n][1024 k]
__device__ __nv_bfloat16 g_whT_l[(size_t)G4 * Hh];// Wh^T lo
__device__ unsigned g_count = 0;
__device__ unsigned g_gen = 0;

// ---------------- helpers ----------------
__device__ __forceinline__ uint32_t smem_u32(const void* p) {
    uint32_t a;
    asm("{ .reg .u64 t; cvta.to.shared.u64 t, %1; cvt.u32.u64 %0, t; }" : "=r"(a) : "l"(p));
    return a;
}

#define LDMX4(r0, r1, r2, r3, addr) \
    asm volatile("ldmatrix.sync.aligned.m8n8.x4.shared.b16 {%0,%1,%2,%3}, [%4];" \
                 : "=r"(r0), "=r"(r1), "=r"(r2), "=r"(r3) : "r"(addr))

#define MMA16816(c0, c1, c2, c3, a0, a1, a2, a3, b0, b1) \
    asm volatile("mma.sync.aligned.m16n8k16.row.col.f32.bf16.bf16.f32 " \
                 "{%0,%1,%2,%3}, {%4,%5,%6,%7}, {%8,%9}, {%0,%1,%2,%3};" \
                 : "+f"(c0), "+f"(c1), "+f"(c2), "+f"(c3) \
                 : "r"(a0), "r"(a1), "r"(a2), "r"(a3), "r"(b0), "r"(b1))

// ---------------- grid barrier ----------------
__device__ __forceinline__ void grid_barrier() {
    __syncthreads();
    if (threadIdx.x == 0) {
        __threadfence();
        unsigned gen = atomicAdd(&g_gen, 0u);
        if (atomicAdd(&g_count, 1u) == NBLK - 1) {
            atomicExch(&g_count, 0u);
            atomicAdd(&g_gen, 1u);
        } else {
            while (atomicAdd(&g_gen, 0u) == gen) __nanosleep(64);
        }
    }
    __syncthreads();
}

// ---------------------------------------------------------------------------
// setup: Wh [1024 k][4096 n] fp32 -> Wh^T hi/lo bf16 [4096 n][1024 k]
// ---------------------------------------------------------------------------
__global__ void __launch_bounds__(256) setup_whT(const float* __restrict__ Wh) {
    __shared__ float tile[32][33];
    int kk = blockIdx.x * 32;
    int nn = blockIdx.y * 32;
    int txx = threadIdx.x & 31;
    int tyy = threadIdx.x >> 5;    // 0..7
#pragma unroll
    for (int j = 0; j < 4; j++) {
        int row = tyy * 4 + j;
        tile[row][txx] = Wh[(size_t)(kk + row) * G4 + nn + txx];
    }
    __syncthreads();
#pragma unroll
    for (int j = 0; j < 4; j++) {
        int row = tyy * 4 + j;                       // n-local
        float v = tile[txx][row];
        __nv_bfloat16 hi = __float2bfloat16(v);
        __nv_bfloat16 lo = __float2bfloat16(v - __bfloat162float(hi));
        size_t o = (size_t)(nn + row) * Hh + kk + txx;
        g_whT_h[o] = hi;
        g_whT_l[o] = lo;
    }
}

// ---------------------------------------------------------------------------
// xW = x[N*T, D] @ Wx[D, 4H] + b  (fp32 FMA2 SGEMM — unchanged, known good)
// ---------------------------------------------------------------------------
__global__ void __launch_bounds__(256) sgemm_xw(const float* __restrict__ A,
                                                const float* __restrict__ B,
                                                const float* __restrict__ bias) {
    __shared__ float Asd[8][256];
    __shared__ float Bs[8][128];

    int tid = threadIdx.x;
    int bx = blockIdx.x;
    int by = blockIdx.y;

    int arow = tid >> 1;
    int acol = (tid & 1) * 4;
    int brow = tid >> 5;
    int bcol = (tid & 31) * 4;

    const float* Ap = A + (size_t)(by * 128 + arow) * Dd + acol;
    const float* Bp = B + (size_t)brow * G4 + bx * 128 + bcol;

    int tx = tid & 15;
    int ty = tid >> 4;

    unsigned long long acc[8][4];
#pragma unroll
    for (int i = 0; i < 8; i++)
#pragma unroll
        for (int j = 0; j < 4; j++) acc[i][j] = 0ull;

    float4 a4 = *(const float4*)Ap;
    float4 b4 = *(const float4*)Bp;

    for (int k0 = 0; k0 < Dd; k0 += 8) {
        Asd[acol + 0][arow * 2] = a4.x; Asd[acol + 0][arow * 2 + 1] = a4.x;
        Asd[acol + 1][arow * 2] = a4.y; Asd[acol + 1][arow * 2 + 1] = a4.y;
        Asd[acol + 2][arow * 2] = a4.z; Asd[acol + 2][arow * 2 + 1] = a4.z;
        Asd[acol + 3][arow * 2] = a4.w; Asd[acol + 3][arow * 2 + 1] = a4.w;
        *(float4*)&Bs[brow][bcol] = b4;
        __syncthreads();

        if (k0 + 8 < Dd) {
            Ap += 8;
            Bp += (size_t)8 * G4;
            a4 = *(const float4*)Ap;
            b4 = *(const float4*)Bp;
        }

#pragma unroll
        for (int kk = 0; kk < 8; kk++) {
            ulonglong2 aa0 = *(const ulonglong2*)&Asd[kk][ty * 16 + 0];
            ulonglong2 aa1 = *(const ulonglong2*)&Asd[kk][ty * 16 + 4];
            ulonglong2 aa2 = *(const ulonglong2*)&Asd[kk][ty * 16 + 8];
            ulonglong2 aa3 = *(const ulonglong2*)&Asd[kk][ty * 16 + 12];
            ulonglong2 bb0 = *(const ulonglong2*)&Bs[kk][tx * 8];
            ulonglong2 bb1 = *(const ulonglong2*)&Bs[kk][tx * 8 + 4];

            FMA2(acc[0][0], aa0.x, bb0.x); FMA2(acc[0][1], aa0.x, bb0.y);
            FMA2(acc[0][2], aa0.x, bb1.x); FMA2(acc[0][3], aa0.x, bb1.y);
            FMA2(acc[1][0], aa0.y, bb0.x); FMA2(acc[1][1], aa0.y, bb0.y);
            FMA2(acc[1][2], aa0.y, bb1.x); FMA2(acc[1][3], aa0.y, bb1.y);
            FMA2(acc[2][0], aa1.x, bb0.x); FMA2(acc[2][1], aa1.x, bb0.y);
            FMA2(acc[2][2], aa1.x, bb1.x); FMA2(acc[2][3], aa1.x, bb1.y);
            FMA2(acc[3][0], aa1.y, bb0.x); FMA2(acc[3][1], aa1.y, bb0.y);
            FMA2(acc[3][2], aa1.y, bb1.x); FMA2(acc[3][3], aa1.y, bb1.y);
            FMA2(acc[4][0], aa2.x, bb0.x); FMA2(acc[4][1], aa2.x, bb0.y);
            FMA2(acc[4][2], aa2.x, bb1.x); FMA2(acc[4][3], aa2.x, bb1.y);
            FMA2(acc[5][0], aa2.y, bb0.x); FMA2(acc[5][1], aa2.y, bb0.y);
            FMA2(acc[5][2], aa2.y, bb1.x); FMA2(acc[5][3], aa2.y, bb1.y);
            FMA2(acc[6][0], aa3.x, bb0.x); FMA2(acc[6][1], aa3.x, bb0.y);
            FMA2(acc[6][2], aa3.x, bb1.x); FMA2(acc[6][3], aa3.x, bb1.y);
            FMA2(acc[7][0], aa3.y, bb0.x); FMA2(acc[7][1], aa3.y, bb0.y);
            FMA2(acc[7][2], aa3.y, bb1.x); FMA2(acc[7][3], aa3.y, bb1.y);
        }
        __syncthreads();
    }

    float bv[8];
    const float* bp = bias + bx * 128 + tx * 8;
#pragma unroll
    for (int j = 0; j < 8; j++) bv[j] = bp[j];

#pragma unroll
    for (int i = 0; i < 8; i++) {
        size_t row = (size_t)(by * 128 + ty * 8 + i);
        float* Cp = g_xw + row * G4 + bx * 128 + tx * 8;
#pragma unroll
        for (int jp = 0; jp < 4; jp++) {
            F2U u; u.u = acc[i][jp];
            Cp[2 * jp + 0] = u.f.x + bv[2 * jp + 0];
            Cp[2 * jp + 1] = u.f.y + bv[2 * jp + 1];
        }
    }
}

// ---------------------------------------------------------------------------
// Persistent LSTM recurrence with mma.sync (HMMA) split-bf16.
// Block (ntile, ks): P[ks][64 rows][c0:c0+128] = h[:, k0:+256] @ Wh[k0:+256, c0:+128]
// 3-term split: AhBh + AhBl + AlBh, all into the same fp32 accumulator.
// B (WhT hi/lo bf16) resident in smem for all 512 steps.
// ---------------------------------------------------------------------------
#define RSTR 264                        // padded row stride (elems) for ldmatrix tiles
#define SB_H   0                        // 128 x 264 bf16 = 67584 B
#define SB_L   67584
#define SA_H   135168                   // 64 x 264 bf16 = 33792 B
#define SA_L   168960
#define SMEM_TOTAL 202752

__global__ void __launch_bounds__(256) lstm_persist(const float* __restrict__ h0,
                                                    float* __restrict__ out) {
    extern __shared__ char smem[];
    uint32_t sbase = smem_u32(smem);
    int tid = threadIdx.x;
    int wid = tid >> 5;
    int lane = tid & 31;
    int bid = blockIdx.x;
    int ntile = bid & 31;             // 0..31 -> 128-col slice
    int ks = bid >> 5;                // 0..3  -> 256-k slice
    int c0 = ntile * 128;
    int k0 = ks * KPER;

    int wm = wid & 3;                 // row group: rows wm*16 .. +16
    int wcg = wid >> 2;               // col group: cols wcg*64 .. +64

    // ---- load resident B tiles once: [n-local 0..127][k-local 0..255] ----
    {
        int nl = tid >> 1;            // 0..127
        int half = tid & 1;           // k half (128 elems = 256B)
        const uint4* srcH = (const uint4*)(g_whT_h + (size_t)(c0 + nl) * Hh + k0 + half * 128);
        const uint4* srcL = (const uint4*)(g_whT_l + (size_t)(c0 + nl) * Hh + k0 + half * 128);
        uint4* dstH = (uint4*)(smem + SB_H + (nl * RSTR + half * 128) * 2);
        uint4* dstL = (uint4*)(smem + SB_L + (nl * RSTR + half * 128) * 2);
#pragma unroll
        for (int i = 0; i < 16; i++) { dstH[i] = srcH[i]; dstL[i] = srcL[i]; }
    }
    __syncthreads();

    // ldmatrix lane addressing (shared by A and B tiles)
    int lrow = lane & 7;
    int lk8  = (lane >> 4) * 8;       // k offset within 16-chunk
    int ln8  = ((lane >> 3) & 1) * 8; // row offset within 16-block

    // per-lane base addresses (elems -> bytes*2)
    uint32_t aH = sbase + SA_H + ((wm * 16 + ln8 + lrow) * RSTR + lk8) * 2;
    uint32_t aL = sbase + SA_L + ((wm * 16 + ln8 + lrow) * RSTR + lk8) * 2;
    uint32_t bH0 = sbase + SB_H + ((wcg * 64 + ln8 + lrow) * RSTR + lk8) * 2;
    uint32_t bL0 = sbase + SB_L + ((wcg * 64 + ln8 + lrow) * RSTR + lk8) * 2;

    // A staging mapping
    int sr = tid >> 2;                // 0..63 (h row)
    int sq = tid & 3;                 // 64-col quarter

    // epilogue mapping
    int eidx0 = bid * 512 + tid;

    for (int t = 0; t < Tt; t++) {
        const float* hprev = (t == 0) ? h0 : (out + (size_t)(t - 1) * Hh);
        int hstride = (t == 0) ? Hh : Tt * Hh;

        // ---- stage A: h rows -> bf16 hi/lo, [64][RSTR] padded layout ----
        {
            const float* hp = hprev + (size_t)sr * hstride + k0 + sq * 64;
            uint32_t dH = sbase + SA_H + (sr * RSTR + sq * 64) * 2;
            uint32_t dL = sbase + SA_L + (sr * RSTR + sq * 64) * 2;
#pragma unroll
            for (int i = 0; i < 64; i += 2) {
                float x0 = hp[i], x1 = hp[i + 1];
                __nv_bfloat16 h0b = __float2bfloat16(x0);
                __nv_bfloat16 h1b = __float2bfloat16(x1);
                __nv_bfloat16 l0b = __float2bfloat16(x0 - __bfloat162float(h0b));
                __nv_bfloat16 l1b = __float2bfloat16(x1 - __bfloat162float(h1b));
                uint32_t hv = (uint32_t)__bfloat16_as_ushort(h0b) |
                              ((uint32_t)__bfloat16_as_ushort(h1b) << 16);
                uint32_t lv = (uint32_t)__bfloat16_as_ushort(l0b) |
                              ((uint32_t)__bfloat16_as_ushort(l1b) << 16);
                asm volatile("st.shared.b32 [%0], %1;" :: "r"(dH + i * 2), "r"(hv));
                asm volatile("st.shared.b32 [%0], %1;" :: "r"(dL + i * 2), "r"(lv));
            }
        }
        __syncthreads();

        // ---- MMA phase: 16 k-chunks, 8 n-tiles, 3 terms each ----
        float acc[8][4];
#pragma unroll
        for (int nt = 0; nt < 8; nt++)
#pragma unroll
            for (int j = 0; j < 4; j++) acc[nt][j] = 0.0f;

#pragma unroll 4
        for (int kc = 0; kc < 16; kc++) {
            uint32_t koff = kc * 32;  // 16 elems * 2B
            uint32_t ah0, ah1, ah2, ah3, al0, al1, al2, al3;
            LDMX4(ah0, ah1, ah2, ah3, aH + koff);
            LDMX4(al0, al1, al2, al3, aL + koff);

            uint32_t bh[8][2], bl[8][2];
#pragma unroll
            for (int q = 0; q < 4; q++) {
                uint32_t r0, r1, r2, r3;
                LDMX4(r0, r1, r2, r3, bH0 + q * (16 * RSTR * 2) + koff);
                bh[2 * q][0] = r0; bh[2 * q][1] = r2;
                bh[2 * q + 1][0] = r1; bh[2 * q + 1][1] = r3;
                LDMX4(r0, r1, r2, r3, bL0 + q * (16 * RSTR * 2) + koff);
                bl[2 * q][0] = r0; bl[2 * q][1] = r2;
                bl[2 * q + 1][0] = r1; bl[2 * q + 1][1] = r3;
            }

#pragma unroll
            for (int nt = 0; nt < 8; nt++) {
                MMA16816(acc[nt][0], acc[nt][1], acc[nt][2], acc[nt][3],
                         ah0, ah1, ah2, ah3, bh[nt][0], bh[nt][1]);
                MMA16816(acc[nt][0], acc[nt][1], acc[nt][2], acc[nt][3],
                         ah0, ah1, ah2, ah3, bl[nt][0], bl[nt][1]);
                MMA16816(acc[nt][0], acc[nt][1], acc[nt][2], acc[nt][3],
                         al0, al1, al2, al3, bh[nt][0], bh[nt][1]);
            }
        }

        // ---- write partials to g_p (block-exclusive region) ----
        {
            int r0w = wm * 16 + (lane >> 2);
            int cb = c0 + wcg * 64 + 2 * (lane & 3);
#pragma unroll
            for (int nt = 0; nt < 8; nt++) {
                int cc = cb + nt * 8;
                *(float2*)&g_p[ks][r0w][cc]     = make_float2(acc[nt][0], acc[nt][1]);
                *(float2*)&g_p[ks][r0w + 8][cc] = make_float2(acc[nt][2], acc[nt][3]);
            }
        }

        grid_barrier();

        // ---- gates epilogue: 2 (n,hc) items per thread ----
#pragma unroll
        for (int it = 0; it < 2; it++) {
            int idx = eidx0 + it * 256;
            int n = idx >> 10;
            int hc = idx & 1023;

            const float* xw = g_xw + (size_t)(n * Tt + t) * G4 + hc;

            float a0 = __ldcg(&g_p[0][n][hc])        + __ldcg(&g_p[1][n][hc])
                     + __ldcg(&g_p[2][n][hc])        + __ldcg(&g_p[3][n][hc])        + xw[0];
            float a1 = __ldcg(&g_p[0][n][1024 + hc]) + __ldcg(&g_p[1][n][1024 + hc])
                     + __ldcg(&g_p[2][n][1024 + hc]) + __ldcg(&g_p[3][n][1024 + hc]) + xw[1024];
            float a2 = __ldcg(&g_p[0][n][2048 + hc]) + __ldcg(&g_p[1][n][2048 + hc])
                     + __ldcg(&g_p[2][n][2048 + hc]) + __ldcg(&g_p[3][n][2048 + hc]) + xw[2048];
            float a3 = __ldcg(&g_p[0][n][3072 + hc]) + __ldcg(&g_p[1][n][3072 + hc])
                     + __ldcg(&g_p[2][n][3072 + hc]) + __ldcg(&g_p[3][n][3072 + hc]) + xw[3072];

            float iv = 1.0f / (1.0f + expf(-a0));
            float fv = 1.0f / (1.0f + expf(-a1));
            float ov = 1.0f / (1.0f + expf(-a2));
            float gv = tanhf(a3);

            float cp = (t == 0) ? 0.0f : g_c[idx];
            float cn = fv * cp + iv * gv;
            float hv = ov * tanhf(cn);

            g_c[idx] = cn;
            out[((size_t)n * Tt + t) * Hh + hc] = hv;
        }

        grid_barrier();
    }
}

// ---------------------------------------------------------------------------
extern "C" void kernel_launch(void* const* d_in, const int* in_sizes, int n_in,
                              void* d_out, int out_size) {
    const float* x  = (const float*)d_in[0];   // [N,T,D]
    const float* h0 = (const float*)d_in[1];   // [N,H]
    const float* Wx = (const float*)d_in[2];   // [D,4H]
    const float* Wh = (const float*)d_in[3];   // [H,4H]
    const float* b  = (const float*)d_in[4];   // [4H]
    float* out = (float*)d_out;                // [N,T,H]

    dim3 gt(Hh / 32, G4 / 32);                 // (32,128)
    setup_whT<<<gt, 256>>>(Wh);

    dim3 g1(G4 / 128, (Nn * Tt) / 128);        // (32, 256)
    sgemm_xw<<<g1, 256>>>(x, Wx, b);

    cudaFuncSetAttribute(lstm_persist, cudaFuncAttributeMaxDynamicSharedMemorySize, SMEM_TOTAL);
    lstm_persist<<<NBLK, 256, SMEM_TOTAL>>>(h0, out);
}

// round 8
// speedup vs baseline: 1.0626x; 1.0626x over previous
#include <cuda_runtime.h>
#include <cuda_bf16.h>
#include <math.h>
#include <stdint.h>

#define Nn 64
#define Tt 512
#define Dd 1024
#define Hh 1024
#define G4 4096   // 4*Hh
#define NBLK 128  // persistent grid (co-resident on 148 SMs)

// ---------------- packed fp32 FMA for the xW GEMM ----------------
#define FMA2(d, a, b) asm("fma.rn.f32x2 %0, %1, %2, %0;" : "+l"(d) : "l"(a), "l"(b))
union F2U { unsigned long long u; float2 f; };

// ---------------- device scratch (allocation-free rule) ----------------
__device__ float g_xw[(size_t)Nn * Tt * G4];         // input projection [N*T,4H]
__device__ __nv_bfloat16 g_whT_h[(size_t)G4 * Hh];   // Wh^T hi  [4096 n][1024 k]
__device__ __nv_bfloat16 g_whT_l[(size_t)G4 * Hh];   // Wh^T lo
__device__ __nv_bfloat16 g_hbf_h[2][Nn * Hh];        // h split hi, double-buffered
__device__ __nv_bfloat16 g_hbf_l[2][Nn * Hh];        // h split lo
__device__ unsigned g_count = 0;
__device__ unsigned g_gen = 0;

// ---------------- helpers ----------------
__device__ __forceinline__ uint32_t smem_u32(const void* p) {
    uint32_t a;
    asm("{ .reg .u64 t; cvta.to.shared.u64 t, %1; cvt.u32.u64 %0, t; }" : "=r"(a) : "l"(p));
    return a;
}

#define LDMX4(r0, r1, r2, r3, addr) \
    asm volatile("ldmatrix.sync.aligned.m8n8.x4.shared.b16 {%0,%1,%2,%3}, [%4];" \
                 : "=r"(r0), "=r"(r1), "=r"(r2), "=r"(r3) : "r"(addr))

#define MMA16816(c0, c1, c2, c3, a0, a1, a2, a3, b0, b1) \
    asm volatile("mma.sync.aligned.m16n8k16.row.col.f32.bf16.bf16.f32 " \
                 "{%0,%1,%2,%3}, {%4,%5,%6,%7}, {%8,%9}, {%0,%1,%2,%3};" \
                 : "+f"(c0), "+f"(c1), "+f"(c2), "+f"(c3) \
                 : "r"(a0), "r"(a1), "r"(a2), "r"(a3), "r"(b0), "r"(b1))

// ---------------- grid barrier (one per step): atomic arrive, volatile poll --
__device__ __forceinline__ void grid_barrier() {
    __syncthreads();
    if (threadIdx.x == 0) {
        __threadfence();
        unsigned gen = *(volatile unsigned*)&g_gen;
        if (atomicAdd(&g_count, 1u) == NBLK - 1) {
            atomicExch(&g_count, 0u);
            __threadfence();
            atomicAdd(&g_gen, 1u);
        } else {
            while (*(volatile unsigned*)&g_gen == gen) { }
        }
        __threadfence();
    }
    __syncthreads();
}

// ---------------------------------------------------------------------------
// setup: Wh [1024 k][4096 n] fp32 -> Wh^T hi/lo bf16 [4096 n][1024 k]
// ---------------------------------------------------------------------------
__global__ void __launch_bounds__(256) setup_whT(const float* __restrict__ Wh) {
    __shared__ float tile[32][33];
    int kk = blockIdx.x * 32;
    int nn = blockIdx.y * 32;
    int txx = threadIdx.x & 31;
    int tyy = threadIdx.x >> 5;
#pragma unroll
    for (int j = 0; j < 4; j++) {
        int row = tyy * 4 + j;
        tile[row][txx] = Wh[(size_t)(kk + row) * G4 + nn + txx];
    }
    __syncthreads();
#pragma unroll
    for (int j = 0; j < 4; j++) {
        int row = tyy * 4 + j;
        float v = tile[txx][row];
        __nv_bfloat16 hi = __float2bfloat16(v);
        __nv_bfloat16 lo = __float2bfloat16(v - __bfloat162float(hi));
        size_t o = (size_t)(nn + row) * Hh + kk + txx;
        g_whT_h[o] = hi;
        g_whT_l[o] = lo;
    }
}

// setup: h0 fp32 -> g_hbf buffer 0 (hi/lo split)
__global__ void __launch_bounds__(256) setup_h0(const float* __restrict__ h0) {
    int i = blockIdx.x * 256 + threadIdx.x;   // 0..65535
    float v = h0[i];
    __nv_bfloat16 hi = __float2bfloat16(v);
    __nv_bfloat16 lo = __float2bfloat16(v - __bfloat162float(hi));
    g_hbf_h[0][i] = hi;
    g_hbf_l[0][i] = lo;
}

// ---------------------------------------------------------------------------
// xW = x[N*T, D] @ Wx[D, 4H] + b  (fp32 FMA2 SGEMM — unchanged)
// ---------------------------------------------------------------------------
__global__ void __launch_bounds__(256) sgemm_xw(const float* __restrict__ A,
                                                const float* __restrict__ B,
                                                const float* __restrict__ bias) {
    __shared__ float Asd[8][256];
    __shared__ float Bs[8][128];

    int tid = threadIdx.x;
    int bx = blockIdx.x;
    int by = blockIdx.y;

    int arow = tid >> 1;
    int acol = (tid & 1) * 4;
    int brow = tid >> 5;
    int bcol = (tid & 31) * 4;

    const float* Ap = A + (size_t)(by * 128 + arow) * Dd + acol;
    const float* Bp = B + (size_t)brow * G4 + bx * 128 + bcol;

    int tx = tid & 15;
    int ty = tid >> 4;

    unsigned long long acc[8][4];
#pragma unroll
    for (int i = 0; i < 8; i++)
#pragma unroll
        for (int j = 0; j < 4; j++) acc[i][j] = 0ull;

    float4 a4 = *(const float4*)Ap;
    float4 b4 = *(const float4*)Bp;

    for (int k0 = 0; k0 < Dd; k0 += 8) {
        Asd[acol + 0][arow * 2] = a4.x; Asd[acol + 0][arow * 2 + 1] = a4.x;
        Asd[acol + 1][arow * 2] = a4.y; Asd[acol + 1][arow * 2 + 1] = a4.y;
        Asd[acol + 2][arow * 2] = a4.z; Asd[acol + 2][arow * 2 + 1] = a4.z;
        Asd[acol + 3][arow * 2] = a4.w; Asd[acol + 3][arow * 2 + 1] = a4.w;
        *(float4*)&Bs[brow][bcol] = b4;
        __syncthreads();

        if (k0 + 8 < Dd) {
            Ap += 8;
            Bp += (size_t)8 * G4;
            a4 = *(const float4*)Ap;
            b4 = *(const float4*)Bp;
        }

#pragma unroll
        for (int kk = 0; kk < 8; kk++) {
            ulonglong2 aa0 = *(const ulonglong2*)&Asd[kk][ty * 16 + 0];
            ulonglong2 aa1 = *(const ulonglong2*)&Asd[kk][ty * 16 + 4];
            ulonglong2 aa2 = *(const ulonglong2*)&Asd[kk][ty * 16 + 8];
            ulonglong2 aa3 = *(const ulonglong2*)&Asd[kk][ty * 16 + 12];
            ulonglong2 bb0 = *(const ulonglong2*)&Bs[kk][tx * 8];
            ulonglong2 bb1 = *(const ulonglong2*)&Bs[kk][tx * 8 + 4];

            FMA2(acc[0][0], aa0.x, bb0.x); FMA2(acc[0][1], aa0.x, bb0.y);
            FMA2(acc[0][2], aa0.x, bb1.x); FMA2(acc[0][3], aa0.x, bb1.y);
            FMA2(acc[1][0], aa0.y, bb0.x); FMA2(acc[1][1], aa0.y, bb0.y);
            FMA2(acc[1][2], aa0.y, bb1.x); FMA2(acc[1][3], aa0.y, bb1.y);
            FMA2(acc[2][0], aa1.x, bb0.x); FMA2(acc[2][1], aa1.x, bb0.y);
            FMA2(acc[2][2], aa1.x, bb1.x); FMA2(acc[2][3], aa1.x, bb1.y);
            FMA2(acc[3][0], aa1.y, bb0.x); FMA2(acc[3][1], aa1.y, bb0.y);
            FMA2(acc[3][2], aa1.y, bb1.x); FMA2(acc[3][3], aa1.y, bb1.y);
            FMA2(acc[4][0], aa2.x, bb0.x); FMA2(acc[4][1], aa2.x, bb0.y);
            FMA2(acc[4][2], aa2.x, bb1.x); FMA2(acc[4][3], aa2.x, bb1.y);
            FMA2(acc[5][0], aa2.y, bb0.x); FMA2(acc[5][1], aa2.y, bb0.y);
            FMA2(acc[5][2], aa2.y, bb1.x); FMA2(acc[5][3], aa2.y, bb1.y);
            FMA2(acc[6][0], aa3.x, bb0.x); FMA2(acc[6][1], aa3.x, bb0.y);
            FMA2(acc[6][2], aa3.x, bb1.x); FMA2(acc[6][3], aa3.x, bb1.y);
            FMA2(acc[7][0], aa3.y, bb0.x); FMA2(acc[7][1], aa3.y, bb0.y);
            FMA2(acc[7][2], aa3.y, bb1.x); FMA2(acc[7][3], aa3.y, bb1.y);
        }
        __syncthreads();
    }

    float bv[8];
    const float* bp = bias + bx * 128 + tx * 8;
#pragma unroll
    for (int j = 0; j < 8; j++) bv[j] = bp[j];

#pragma unroll
    for (int i = 0; i < 8; i++) {
        size_t row = (size_t)(by * 128 + ty * 8 + i);
        float* Cp = g_xw + row * G4 + bx * 128 + tx * 8;
#pragma unroll
        for (int jp = 0; jp < 4; jp++) {
            F2U u; u.u = acc[i][jp];
            Cp[2 * jp + 0] = u.f.x + bv[2 * jp + 0];
            Cp[2 * jp + 1] = u.f.y + bv[2 * jp + 1];
        }
    }
}

// ---------------------------------------------------------------------------
// Persistent LSTM, one grid barrier per step, fully block-local epilogue.
// Block owns 8 h-cols x 4 gates (32 output cols), all 64 rows, full K=1024.
// Weights (32 WhT rows hi+lo) resident in smem all 512 steps.
// A (h hi/lo bf16) streamed from double-buffered g_hbf via __ldcg.
// ---------------------------------------------------------------------------
#define RSTRB 1032                       // B row stride (elems)
#define RSTRA 136                        // A row stride (elems) per 128-k chunk
#define SB_H   0                         // 32*1032*2 = 66048
#define SB_L   66048                     // -> 132096
#define SA     132096                    // 2 bufs x (hi 17408 + lo 17408) = 69632
#define ABYT   17408
#define SAT    201728                    // At[64][40] f32 = 10240
#define SMEM_TOTAL 211968

__global__ void __launch_bounds__(256) lstm_persist(float* __restrict__ out) {
    extern __shared__ char smem[];
    uint32_t sbase = smem_u32(smem);
    float* At = (float*)(smem + SAT);     // [64][40]
    int tid = threadIdx.x;
    int wid = tid >> 5;
    int lane = tid & 31;
    int bid = blockIdx.x;
    int hb = bid * 8;                     // 8 h-cols owned by this block

    int wm = wid & 3;                     // m16 group
    int wcg = wid >> 2;                   // n16 group (0: cols 0-15, 1: 16-31)

    // ---- load resident B (32 rows x 1024 k, hi+lo) once ----
    {
        int nl = tid >> 3;                // 0..31 local col
        int seg = tid & 7;                // 8 threads per row, 16 uint4 each
        int rg = (nl >> 3) * 1024 + hb + (nl & 7);   // gate*1024 + hb + j
        const uint4* srcH = (const uint4*)(g_whT_h + (size_t)rg * Hh) + seg * 16;
        const uint4* srcL = (const uint4*)(g_whT_l + (size_t)rg * Hh) + seg * 16;
        char* dH = smem + SB_H + nl * (RSTRB * 2) + seg * 256;
        char* dL = smem + SB_L + nl * (RSTRB * 2) + seg * 256;
#pragma unroll
        for (int i = 0; i < 16; i++) {
            ((uint4*)dH)[i] = srcH[i];
            ((uint4*)dL)[i] = srcL[i];
        }
    }
    __syncthreads();

    // ldmatrix lane addressing
    int lrow = lane & 7;
    int lk8  = (lane >> 4) * 8;
    int ln8  = ((lane >> 3) & 1) * 8;

    uint32_t laneA = ((uint32_t)(wm * 16 + ln8 + lrow) * RSTRA + lk8) * 2;
    uint32_t bLaneH = sbase + SB_H + ((uint32_t)(wcg * 16 + ln8 + lrow) * RSTRB + lk8) * 2;
    uint32_t bLaneL = bLaneH + (SB_L - SB_H);

    // A staging mapping: 4 uint4 per thread per array per chunk
    int srow = tid >> 2;                  // 0..63
    int sq = tid & 3;                     // 32-elem quarter of the 128-k chunk

    // epilogue / state
    float creg[2] = {0.0f, 0.0f};
    int en[2], ej[2];
#pragma unroll
    for (int it = 0; it < 2; it++) {
        int item = tid + it * 256;
        en[it] = item >> 3;
        ej[it] = item & 7;
    }

    for (int t = 0; t < Tt; t++) {
        int rb = t & 1;                   // g_hbf read buffer
        const __nv_bfloat16* hH = g_hbf_h[rb];
        const __nv_bfloat16* hL = g_hbf_l[rb];

        // ---- stage chunk 0 ----
        {
            const uint4* sH = (const uint4*)(hH + (size_t)srow * Hh) + sq * 4;
            const uint4* sL = (const uint4*)(hL + (size_t)srow * Hh) + sq * 4;
            char* dH = smem + SA + srow * (RSTRA * 2) + sq * 64;
            char* dL = dH + ABYT;
#pragma unroll
            for (int i = 0; i < 4; i++) {
                ((uint4*)dH)[i] = __ldcg(sH + i);
                ((uint4*)dL)[i] = __ldcg(sL + i);
            }
        }
        __syncthreads();

        float acc[2][4];
#pragma unroll
        for (int nt = 0; nt < 2; nt++)
#pragma unroll
            for (int j = 0; j < 4; j++) acc[nt][j] = 0.0f;

        int p = 0;
        for (int c = 0; c < 8; c++) {
            if (c < 8 - 1) {              // prefetch next chunk into alt buffer
                const uint4* sH = (const uint4*)(hH + (size_t)srow * Hh + (c + 1) * 128) + sq * 4;
                const uint4* sL = (const uint4*)(hL + (size_t)srow * Hh + (c + 1) * 128) + sq * 4;
                char* dH = smem + SA + (p ^ 1) * (2 * ABYT) + srow * (RSTRA * 2) + sq * 64;
                char* dL = dH + ABYT;
#pragma unroll
                for (int i = 0; i < 4; i++) {
                    ((uint4*)dH)[i] = __ldcg(sH + i);
                    ((uint4*)dL)[i] = __ldcg(sL + i);
                }
            }

            uint32_t aH = sbase + SA + p * (2 * ABYT) + laneA;
            uint32_t aL = aH + ABYT;
            uint32_t bOff = (uint32_t)c * 256;
#pragma unroll
            for (int kc = 0; kc < 8; kc++) {
                uint32_t ko = kc * 32;
                uint32_t ah0, ah1, ah2, ah3, al0, al1, al2, al3;
                LDMX4(ah0, ah1, ah2, ah3, aH + ko);
                LDMX4(al0, al1, al2, al3, aL + ko);
                uint32_t r0, r1, r2, r3, s0, s1, s2, s3;
                LDMX4(r0, r1, r2, r3, bLaneH + bOff + ko);
                LDMX4(s0, s1, s2, s3, bLaneL + bOff + ko);

                MMA16816(acc[0][0], acc[0][1], acc[0][2], acc[0][3],
                         ah0, ah1, ah2, ah3, r0, r2);
                MMA16816(acc[1][0], acc[1][1], acc[1][2], acc[1][3],
                         ah0, ah1, ah2, ah3, r1, r3);
                MMA16816(acc[0][0], acc[0][1], acc[0][2], acc[0][3],
                         ah0, ah1, ah2, ah3, s0, s2);
                MMA16816(acc[1][0], acc[1][1], acc[1][2], acc[1][3],
                         ah0, ah1, ah2, ah3, s1, s3);
                MMA16816(acc[0][0], acc[0][1], acc[0][2], acc[0][3],
                         al0, al1, al2, al3, r0, r2);
                MMA16816(acc[1][0], acc[1][1], acc[1][2], acc[1][3],
                         al0, al1, al2, al3, r1, r3);
            }
            __syncthreads();
            p ^= 1;
        }

        // ---- stage accumulators into At[64][40] ----
        {
            int r = wm * 16 + (lane >> 2);
            int cb = wcg * 16 + 2 * (lane & 3);
#pragma unroll
            for (int nt = 0; nt < 2; nt++) {
                int cc = cb + nt * 8;
                At[r * 40 + cc]       = acc[nt][0];
                At[r * 40 + cc + 1]   = acc[nt][1];
                At[(r + 8) * 40 + cc]     = acc[nt][2];
                At[(r + 8) * 40 + cc + 1] = acc[nt][3];
            }
        }
        __syncthreads();

        // ---- block-local gates epilogue (2 items/thread) ----
        int wb = (t + 1) & 1;             // g_hbf write buffer
#pragma unroll
        for (int it = 0; it < 2; it++) {
            int n = en[it], j = ej[it];
            const float* xw = g_xw + (size_t)(n * Tt + t) * G4 + hb + j;

            float a0 = At[n * 40 + j]      + xw[0];       // i
            float a1 = At[n * 40 + 8 + j]  + xw[1024];    // f
            float a2 = At[n * 40 + 16 + j] + xw[2048];    // o
            float a3 = At[n * 40 + 24 + j] + xw[3072];    // g

            float iv = 1.0f / (1.0f + expf(-a0));
            float fv = 1.0f / (1.0f + expf(-a1));
            float ov = 1.0f / (1.0f + expf(-a2));
            float gv = tanhf(a3);

            float cn = fv * creg[it] + iv * gv;
            float hv = ov * tanhf(cn);
            creg[it] = cn;

            out[((size_t)n * Tt + t) * Hh + hb + j] = hv;

            __nv_bfloat16 hi = __float2bfloat16(hv);
            __nv_bfloat16 lo = __float2bfloat16(hv - __bfloat162float(hi));
            g_hbf_h[wb][n * Hh + hb + j] = hi;
            g_hbf_l[wb][n * Hh + hb + j] = lo;
        }

        grid_barrier();
    }
}

// ---------------------------------------------------------------------------
extern "C" void kernel_launch(void* const* d_in, const int* in_sizes, int n_in,
                              void* d_out, int out_size) {
    const float* x  = (const float*)d_in[0];   // [N,T,D]
    const float* h0 = (const float*)d_in[1];   // [N,H]
    const float* Wx = (const float*)d_in[2];   // [D,4H]
    const float* Wh = (const float*)d_in[3];   // [H,4H]
    const float* b  = (const float*)d_in[4];   // [4H]
    float* out = (float*)d_out;                // [N,T,H]

    dim3 gt(Hh / 32, G4 / 32);                 // (32,128)
    setup_whT<<<gt, 256>>>(Wh);
    setup_h0<<<(Nn * Hh) / 256, 256>>>(h0);

    dim3 g1(G4 / 128, (Nn * Tt) / 128);        // (32, 256)
    sgemm_xw<<<g1, 256>>>(x, Wx, b);

    cudaFuncSetAttribute(lstm_persist, cudaFuncAttributeMaxDynamicSharedMemorySize, SMEM_TOTAL);
    lstm_persist<<<NBLK, 256, SMEM_TOTAL>>>(out);
}

// round 10
// speedup vs baseline: 1.2931x; 1.2169x over previous
#include <cuda_runtime.h>
#include <cuda_bf16.h>
#include <math.h>
#include <stdint.h>

#define Nn 64
#define Tt 512
#define Dd 1024
#define Hh 1024
#define G4 4096   // 4*Hh
#define NBLK 128  // persistent grid (co-resident on 148 SMs)

// ---------------- packed fp32 FMA for the xW GEMM ----------------
#define FMA2(d, a, b) asm("fma.rn.f32x2 %0, %1, %2, %0;" : "+l"(d) : "l"(a), "l"(b))
union F2U { unsigned long long u; float2 f; };

// ---------------- device scratch (allocation-free rule) ----------------
__device__ float g_xw[(size_t)Nn * Tt * G4];         // input projection [N*T,4H]
__device__ __nv_bfloat16 g_whT_h[(size_t)G4 * Hh];   // Wh^T hi  [4096 n][1024 k]
__device__ __nv_bfloat16 g_whT_l[(size_t)G4 * Hh];   // Wh^T lo
__device__ __nv_bfloat16 g_hbf_h[2][Nn * Hh];        // h split hi, double-buffered
__device__ __nv_bfloat16 g_hbf_l[2][Nn * Hh];        // h split lo
__device__ unsigned g_count = 0;
__device__ unsigned g_gen = 0;

// ---------------- helpers ----------------
__device__ __forceinline__ uint32_t smem_u32(const void* p) {
    uint32_t a;
    asm("{ .reg .u64 t; cvta.to.shared.u64 t, %1; cvt.u32.u64 %0, t; }" : "=r"(a) : "l"(p));
    return a;
}

#define LDMX4(r0, r1, r2, r3, addr) \
    asm volatile("ldmatrix.sync.aligned.m8n8.x4.shared.b16 {%0,%1,%2,%3}, [%4];" \
                 : "=r"(r0), "=r"(r1), "=r"(r2), "=r"(r3) : "r"(addr))

#define MMA16816(c0, c1, c2, c3, a0, a1, a2, a3, b0, b1) \
    asm volatile("mma.sync.aligned.m16n8k16.row.col.f32.bf16.bf16.f32 " \
                 "{%0,%1,%2,%3}, {%4,%5,%6,%7}, {%8,%9}, {%0,%1,%2,%3};" \
                 : "+f"(c0), "+f"(c1), "+f"(c2), "+f"(c3) \
                 : "r"(a0), "r"(a1), "r"(a2), "r"(a3), "r"(b0), "r"(b1))

// cp.async: 16B global->shared, L2-only (.cg) — also solves cross-step L1 staleness
#define CP_ASYNC16(saddr, gptr) \
    asm volatile("cp.async.cg.shared.global [%0], [%1], 16;" :: "r"(saddr), "l"(gptr))
#define CP_COMMIT() asm volatile("cp.async.commit_group;" ::: "memory")
#define CP_WAIT0()  asm volatile("cp.async.wait_group 0;" ::: "memory")

// fast gates
__device__ __forceinline__ float fsigmoid(float x) {
    return __fdividef(1.0f, 1.0f + __expf(-x));
}
__device__ __forceinline__ float ftanh(float x) {
    float r;
    asm("tanh.approx.f32 %0, %1;" : "=f"(r) : "f"(x));
    return r;
}

// ---------------- grid barrier: atomic arrive, volatile poll ----------------
__device__ __forceinline__ void grid_barrier() {
    __syncthreads();
    if (threadIdx.x == 0) {
        __threadfence();
        unsigned gen = *(volatile unsigned*)&g_gen;
        if (atomicAdd(&g_count, 1u) == NBLK - 1) {
            atomicExch(&g_count, 0u);
            __threadfence();
            atomicAdd(&g_gen, 1u);
        } else {
            while (*(volatile unsigned*)&g_gen == gen) { }
        }
        __threadfence();
    }
    __syncthreads();
}

// ---------------------------------------------------------------------------
// setup: Wh [1024 k][4096 n] fp32 -> Wh^T hi/lo bf16 [4096 n][1024 k]
// ---------------------------------------------------------------------------
__global__ void __launch_bounds__(256) setup_whT(const float* __restrict__ Wh) {
    __shared__ float tile[32][33];
    int kk = blockIdx.x * 32;
    int nn = blockIdx.y * 32;
    int txx = threadIdx.x & 31;
    int tyy = threadIdx.x >> 5;
#pragma unroll
    for (int j = 0; j < 4; j++) {
        int row = tyy * 4 + j;
        tile[row][txx] = Wh[(size_t)(kk + row) * G4 + nn + txx];
    }
    __syncthreads();
#pragma unroll
    for (int j = 0; j < 4; j++) {
        int row = tyy * 4 + j;
        float v = tile[txx][row];
        __nv_bfloat16 hi = __float2bfloat16(v);
        __nv_bfloat16 lo = __float2bfloat16(v - __bfloat162float(hi));
        size_t o = (size_t)(nn + row) * Hh + kk + txx;
        g_whT_h[o] = hi;
        g_whT_l[o] = lo;
    }
}

// setup: h0 fp32 -> g_hbf buffer 0 (hi/lo split)
__global__ void __launch_bounds__(256) setup_h0(const float* __restrict__ h0) {
    int i = blockIdx.x * 256 + threadIdx.x;   // 0..65535
    float v = h0[i];
    __nv_bfloat16 hi = __float2bfloat16(v);
    __nv_bfloat16 lo = __float2bfloat16(v - __bfloat162float(hi));
    g_hbf_h[0][i] = hi;
    g_hbf_l[0][i] = lo;
}

// ---------------------------------------------------------------------------
// xW = x[N*T, D] @ Wx[D, 4H] + b  (fp32 FMA2 SGEMM — known good)
// ---------------------------------------------------------------------------
__global__ void __launch_bounds__(256) sgemm_xw(const float* __restrict__ A,
                                                const float* __restrict__ B,
                                                const float* __restrict__ bias) {
    __shared__ float Asd[8][256];
    __shared__ float Bs[8][128];

    int tid = threadIdx.x;
    int bx = blockIdx.x;
    int by = blockIdx.y;

    int arow = tid >> 1;
    int acol = (tid & 1) * 4;
    int brow = tid >> 5;
    int bcol = (tid & 31) * 4;

    const float* Ap = A + (size_t)(by * 128 + arow) * Dd + acol;
    const float* Bp = B + (size_t)brow * G4 + bx * 128 + bcol;

    int tx = tid & 15;
    int ty = tid >> 4;

    unsigned long long acc[8][4];
#pragma unroll
    for (int i = 0; i < 8; i++)
#pragma unroll
        for (int j = 0; j < 4; j++) acc[i][j] = 0ull;

    float4 a4 = *(const float4*)Ap;
    float4 b4 = *(const float4*)Bp;

    for (int k0 = 0; k0 < Dd; k0 += 8) {
        Asd[acol + 0][arow * 2] = a4.x; Asd[acol + 0][arow * 2 + 1] = a4.x;
        Asd[acol + 1][arow * 2] = a4.y; Asd[acol + 1][arow * 2 + 1] = a4.y;
        Asd[acol + 2][arow * 2] = a4.z; Asd[acol + 2][arow * 2 + 1] = a4.z;
        Asd[acol + 3][arow * 2] = a4.w; Asd[acol + 3][arow * 2 + 1] = a4.w;
        *(float4*)&Bs[brow][bcol] = b4;
        __syncthreads();

        if (k0 + 8 < Dd) {
            Ap += 8;
            Bp += (size_t)8 * G4;
            a4 = *(const float4*)Ap;
            b4 = *(const float4*)Bp;
        }

#pragma unroll
        for (int kk = 0; kk < 8; kk++) {
            ulonglong2 aa0 = *(const ulonglong2*)&Asd[kk][ty * 16 + 0];
            ulonglong2 aa1 = *(const ulonglong2*)&Asd[kk][ty * 16 + 4];
            ulonglong2 aa2 = *(const ulonglong2*)&Asd[kk][ty * 16 + 8];
            ulonglong2 aa3 = *(const ulonglong2*)&Asd[kk][ty * 16 + 12];
            ulonglong2 bb0 = *(const ulonglong2*)&Bs[kk][tx * 8];
            ulonglong2 bb1 = *(const ulonglong2*)&Bs[kk][tx * 8 + 4];

            FMA2(acc[0][0], aa0.x, bb0.x); FMA2(acc[0][1], aa0.x, bb0.y);
            FMA2(acc[0][2], aa0.x, bb1.x); FMA2(acc[0][3], aa0.x, bb1.y);
            FMA2(acc[1][0], aa0.y, bb0.x); FMA2(acc[1][1], aa0.y, bb0.y);
            FMA2(acc[1][2], aa0.y, bb1.x); FMA2(acc[1][3], aa0.y, bb1.y);
            FMA2(acc[2][0], aa1.x, bb0.x); FMA2(acc[2][1], aa1.x, bb0.y);
            FMA2(acc[2][2], aa1.x, bb1.x); FMA2(acc[2][3], aa1.x, bb1.y);
            FMA2(acc[3][0], aa1.y, bb0.x); FMA2(acc[3][1], aa1.y, bb0.y);
            FMA2(acc[3][2], aa1.y, bb1.x); FMA2(acc[3][3], aa1.y, bb1.y);
            FMA2(acc[4][0], aa2.x, bb0.x); FMA2(acc[4][1], aa2.x, bb0.y);
            FMA2(acc[4][2], aa2.x, bb1.x); FMA2(acc[4][3], aa2.x, bb1.y);
            FMA2(acc[5][0], aa2.y, bb0.x); FMA2(acc[5][1], aa2.y, bb0.y);
            FMA2(acc[5][2], aa2.y, bb1.x); FMA2(acc[5][3], aa2.y, bb1.y);
            FMA2(acc[6][0], aa3.x, bb0.x); FMA2(acc[6][1], aa3.x, bb0.y);
            FMA2(acc[6][2], aa3.x, bb1.x); FMA2(acc[6][3], aa3.x, bb1.y);
            FMA2(acc[7][0], aa3.y, bb0.x); FMA2(acc[7][1], aa3.y, bb0.y);
            FMA2(acc[7][2], aa3.y, bb1.x); FMA2(acc[7][3], aa3.y, bb1.y);
        }
        __syncthreads();
    }

    float bv[8];
    const float* bp = bias + bx * 128 + tx * 8;
#pragma unroll
    for (int j = 0; j < 8; j++) bv[j] = bp[j];

#pragma unroll
    for (int i = 0; i < 8; i++) {
        size_t row = (size_t)(by * 128 + ty * 8 + i);
        float* Cp = g_xw + row * G4 + bx * 128 + tx * 8;
#pragma unroll
        for (int jp = 0; jp < 4; jp++) {
            F2U u; u.u = acc[i][jp];
            Cp[2 * jp + 0] = u.f.x + bv[2 * jp + 0];
            Cp[2 * jp + 1] = u.f.y + bv[2 * jp + 1];
        }
    }
}

// ---------------------------------------------------------------------------
// Persistent LSTM (R8-proven structure) + xw prefetch + cp.async + fast gates.
// ---------------------------------------------------------------------------
#define RSTRB 1032
#define RSTRA 136
#define SB_H   0
#define SB_L   66048
#define SA     132096
#define ABYT   17408
#define SAT    201728
#define SMEM_TOTAL 211968

__global__ void __launch_bounds__(256) lstm_persist(float* __restrict__ out) {
    extern __shared__ char smem[];
    uint32_t sbase = smem_u32(smem);
    float* At = (float*)(smem + SAT);     // [64][40]
    int tid = threadIdx.x;
    int wid = tid >> 5;
    int lane = tid & 31;
    int bid = blockIdx.x;
    int hb = bid * 8;

    int wm = wid & 3;
    int wcg = wid >> 2;

    // ---- load resident B (32 rows x 1024 k, hi+lo) once ----
    {
        int nl = tid >> 3;
        int seg = tid & 7;
        int rg = (nl >> 3) * 1024 + hb + (nl & 7);
        const uint4* srcH = (const uint4*)(g_whT_h + (size_t)rg * Hh) + seg * 16;
        const uint4* srcL = (const uint4*)(g_whT_l + (size_t)rg * Hh) + seg * 16;
        char* dH = smem + SB_H + nl * (RSTRB * 2) + seg * 256;
        char* dL = smem + SB_L + nl * (RSTRB * 2) + seg * 256;
#pragma unroll
        for (int i = 0; i < 16; i++) {
            ((uint4*)dH)[i] = srcH[i];
            ((uint4*)dL)[i] = srcL[i];
        }
    }
    __syncthreads();

    int lrow = lane & 7;
    int lk8  = (lane >> 4) * 8;
    int ln8  = ((lane >> 3) & 1) * 8;

    uint32_t laneA = ((uint32_t)(wm * 16 + ln8 + lrow) * RSTRA + lk8) * 2;
    uint32_t bLaneH = sbase + SB_H + ((uint32_t)(wcg * 16 + ln8 + lrow) * RSTRB + lk8) * 2;
    uint32_t bLaneL = bLaneH + (SB_L - SB_H);

    // A staging mapping: 4 uint4 per thread per array per 128-k chunk
    int srow = tid >> 2;                  // 0..63
    int sq = tid & 3;                     // 32-elem quarter
    uint32_t stH = sbase + SA + (uint32_t)(srow * (RSTRA * 2) + sq * 64);

    float creg[2] = {0.0f, 0.0f};
    int en[2], ej[2];
#pragma unroll
    for (int it = 0; it < 2; it++) {
        int item = tid + it * 256;
        en[it] = item >> 3;
        ej[it] = item & 7;
    }

    for (int t = 0; t < Tt; t++) {
        // ---- prefetch epilogue xw operands (independent of h) ----
        float xwv[2][4];
#pragma unroll
        for (int it = 0; it < 2; it++) {
            const float* xw = g_xw + (size_t)(en[it] * Tt + t) * G4 + hb + ej[it];
            xwv[it][0] = __ldcg(xw);
            xwv[it][1] = __ldcg(xw + 1024);
            xwv[it][2] = __ldcg(xw + 2048);
            xwv[it][3] = __ldcg(xw + 3072);
        }

        int rb = t & 1;
        const __nv_bfloat16* hH = g_hbf_h[rb];
        const __nv_bfloat16* hL = g_hbf_l[rb];
        const uint4* gH = (const uint4*)(hH + (size_t)srow * Hh) + sq * 4;
        const uint4* gL = (const uint4*)(hL + (size_t)srow * Hh) + sq * 4;

        // ---- stage chunk 0 via cp.async (L2-only path) ----
        {
            uint32_t dH = stH;
            uint32_t dL = dH + ABYT;
#pragma unroll
            for (int i = 0; i < 4; i++) {
                CP_ASYNC16(dH + i * 16, gH + i);
                CP_ASYNC16(dL + i * 16, gL + i);
            }
            CP_COMMIT();
        }
        CP_WAIT0();
        __syncthreads();

        float acc[2][4];
#pragma unroll
        for (int nt = 0; nt < 2; nt++)
#pragma unroll
            for (int j = 0; j < 4; j++) acc[nt][j] = 0.0f;

        int p = 0;
        for (int c = 0; c < 8; c++) {
            if (c < 7) {
                const uint4* nH = gH + (c + 1) * 16;   // +128 elems = 16 uint4
                const uint4* nL = gL + (c + 1) * 16;
                uint32_t dH = stH + (uint32_t)((p ^ 1) * (2 * ABYT));
                uint32_t dL = dH + ABYT;
#pragma unroll
                for (int i = 0; i < 4; i++) {
                    CP_ASYNC16(dH + i * 16, nH + i);
                    CP_ASYNC16(dL + i * 16, nL + i);
                }
                CP_COMMIT();
            }

            uint32_t aH = sbase + SA + p * (2 * ABYT) + laneA;
            uint32_t aL = aH + ABYT;
            uint32_t bOff = (uint32_t)c * 256;
#pragma unroll
            for (int kc = 0; kc < 8; kc++) {
                uint32_t ko = kc * 32;
                uint32_t ah0, ah1, ah2, ah3, al0, al1, al2, al3;
                LDMX4(ah0, ah1, ah2, ah3, aH + ko);
                LDMX4(al0, al1, al2, al3, aL + ko);
                uint32_t r0, r1, r2, r3, s0, s1, s2, s3;
                LDMX4(r0, r1, r2, r3, bLaneH + bOff + ko);
                LDMX4(s0, s1, s2, s3, bLaneL + bOff + ko);

                MMA16816(acc[0][0], acc[0][1], acc[0][2], acc[0][3],
                         ah0, ah1, ah2, ah3, r0, r2);
                MMA16816(acc[1][0], acc[1][1], acc[1][2], acc[1][3],
                         ah0, ah1, ah2, ah3, r1, r3);
                MMA16816(acc[0][0], acc[0][1], acc[0][2], acc[0][3],
                         ah0, ah1, ah2, ah3, s0, s2);
                MMA16816(acc[1][0], acc[1][1], acc[1][2], acc[1][3],
                         ah0, ah1, ah2, ah3, s1, s3);
                MMA16816(acc[0][0], acc[0][1], acc[0][2], acc[0][3],
                         al0, al1, al2, al3, r0, r2);
                MMA16816(acc[1][0], acc[1][1], acc[1][2], acc[1][3],
                         al0, al1, al2, al3, r1, r3);
            }
            if (c < 7) CP_WAIT0();
            __syncthreads();
            p ^= 1;
        }

        // ---- stage accumulators into At[64][40] ----
        {
            int r = wm * 16 + (lane >> 2);
            int cb = wcg * 16 + 2 * (lane & 3);
#pragma unroll
            for (int nt = 0; nt < 2; nt++) {
                int cc = cb + nt * 8;
                At[r * 40 + cc]       = acc[nt][0];
                At[r * 40 + cc + 1]   = acc[nt][1];
                At[(r + 8) * 40 + cc]     = acc[nt][2];
                At[(r + 8) * 40 + cc + 1] = acc[nt][3];
            }
        }
        __syncthreads();

        // ---- block-local gates epilogue (2 items/thread) ----
        int wb = (t + 1) & 1;
#pragma unroll
        for (int it = 0; it < 2; it++) {
            int n = en[it], j = ej[it];

            float a0 = At[n * 40 + j]      + xwv[it][0];   // i
            float a1 = At[n * 40 + 8 + j]  + xwv[it][1];   // f
            float a2 = At[n * 40 + 16 + j] + xwv[it][2];   // o
            float a3 = At[n * 40 + 24 + j] + xwv[it][3];   // g

            float iv = fsigmoid(a0);
            float fv = fsigmoid(a1);
            float ov = fsigmoid(a2);
            float gv = ftanh(a3);

            float cn = fv * creg[it] + iv * gv;
            float hv = ov * ftanh(cn);
            creg[it] = cn;

            out[((size_t)n * Tt + t) * Hh + hb + j] = hv;

            __nv_bfloat16 hi = __float2bfloat16(hv);
            __nv_bfloat16 lo = __float2bfloat16(hv - __bfloat162float(hi));
            g_hbf_h[wb][n * Hh + hb + j] = hi;
            g_hbf_l[wb][n * Hh + hb + j] = lo;
        }

        grid_barrier();
    }
}

// ---------------------------------------------------------------------------
extern "C" void kernel_launch(void* const* d_in, const int* in_sizes, int n_in,
                              void* d_out, int out_size) {
    const float* x  = (const float*)d_in[0];   // [N,T,D]
    const float* h0 = (const float*)d_in[1];   // [N,H]
    const float* Wx = (const float*)d_in[2];   // [D,4H]
    const float* Wh = (const float*)d_in[3];   // [H,4H]
    const float* b  = (const float*)d_in[4];   // [4H]
    float* out = (float*)d_out;                // [N,T,H]

    dim3 gt(Hh / 32, G4 / 32);                 // (32,128)
    setup_whT<<<gt, 256>>>(Wh);
    setup_h0<<<(Nn * Hh) / 256, 256>>>(h0);

    dim3 g1(G4 / 128, (Nn * Tt) / 128);        // (32, 256)
    sgemm_xw<<<g1, 256>>>(x, Wx, b);

    cudaFuncSetAttribute(lstm_persist, cudaFuncAttributeMaxDynamicSharedMemorySize, SMEM_TOTAL);
    lstm_persist<<<NBLK, 256, SMEM_TOTAL>>>(out);
}

// round 14
// speedup vs baseline: 1.4721x; 1.1384x over previous
#include <cuda_runtime.h>
#include <cuda_bf16.h>
#include <math.h>
#include <stdint.h>

#define Nn 64
#define Tt 512
#define Dd 1024
#define Hh 1024
#define G4 4096   // 4*Hh
#define NBLK 128  // persistent grid (co-resident on 148 SMs)

// ---------------- device scratch (allocation-free rule) ----------------
__device__ float g_xw[(size_t)Nn * Tt * G4];         // input projection [N*T,4H]
__device__ __nv_bfloat16 g_whT_h[(size_t)G4 * Hh];   // Wh^T hi  [4096 n][1024 k]
__device__ __nv_bfloat16 g_whT_l[(size_t)G4 * Hh];   // Wh^T lo
__device__ __nv_bfloat16 g_wxT_h[(size_t)G4 * Dd];   // Wx^T hi  [4096 n][1024 k]
__device__ __nv_bfloat16 g_wxT_l[(size_t)G4 * Dd];   // Wx^T lo
__device__ __nv_bfloat16 g_xbf_h[(size_t)Nn * Tt * Dd]; // x hi [32768 m][1024 k]
__device__ __nv_bfloat16 g_xbf_l[(size_t)Nn * Tt * Dd]; // x lo
__device__ __nv_bfloat16 g_hbf_h[2][Nn * Hh];        // h split hi, double-buffered
__device__ __nv_bfloat16 g_hbf_l[2][Nn * Hh];        // h split lo
__device__ unsigned g_count = 0;
__device__ unsigned g_gen = 0;

// ---------------- helpers ----------------
__device__ __forceinline__ uint32_t smem_u32(const void* p) {
    uint32_t a;
    asm("{ .reg .u64 t; cvta.to.shared.u64 t, %1; cvt.u32.u64 %0, t; }" : "=r"(a) : "l"(p));
    return a;
}

#define LDMX4(r0, r1, r2, r3, addr) \
    asm volatile("ldmatrix.sync.aligned.m8n8.x4.shared.b16 {%0,%1,%2,%3}, [%4];" \
                 : "=r"(r0), "=r"(r1), "=r"(r2), "=r"(r3) : "r"(addr))

#define MMA16816(c0, c1, c2, c3, a0, a1, a2, a3, b0, b1) \
    asm volatile("mma.sync.aligned.m16n8k16.row.col.f32.bf16.bf16.f32 " \
                 "{%0,%1,%2,%3}, {%4,%5,%6,%7}, {%8,%9}, {%0,%1,%2,%3};" \
                 : "+f"(c0), "+f"(c1), "+f"(c2), "+f"(c3) \
                 : "r"(a0), "r"(a1), "r"(a2), "r"(a3), "r"(b0), "r"(b1))

// cp.async: 16B global->shared, L2-only (.cg)
#define CP_ASYNC16(saddr, gptr) \
    asm volatile("cp.async.cg.shared.global [%0], [%1], 16;" :: "r"(saddr), "l"(gptr))
#define CP_COMMIT() asm volatile("cp.async.commit_group;" ::: "memory")
#define CP_WAIT0()  asm volatile("cp.async.wait_group 0;" ::: "memory")

// fast gates
__device__ __forceinline__ float fsigmoid(float x) {
    return __fdividef(1.0f, 1.0f + __expf(-x));
}
__device__ __forceinline__ float ftanh(float x) {
    float r;
    asm("tanh.approx.f32 %0, %1;" : "=f"(r) : "f"(x));
    return r;
}

// ---------------- grid barrier: atomic arrive, volatile poll ----------------
__device__ __forceinline__ void grid_barrier() {
    __syncthreads();
    if (threadIdx.x == 0) {
        __threadfence();
        unsigned gen = *(volatile unsigned*)&g_gen;
        if (atomicAdd(&g_count, 1u) == NBLK - 1) {
            atomicExch(&g_count, 0u);
            __threadfence();
            atomicAdd(&g_gen, 1u);
        } else {
            while (*(volatile unsigned*)&g_gen == gen) { }
        }
        __threadfence();
    }
    __syncthreads();
}

// ---------------------------------------------------------------------------
// setup: W [1024 k][4096 n] fp32 -> W^T hi/lo bf16 [4096 n][1024 k]
// sel = 0 -> g_whT, sel = 1 -> g_wxT.   (Device globals referenced ONLY in
// device code — passing __device__ symbols as host-side kernel args was the
// R9/R11 failure root cause.)
// ---------------------------------------------------------------------------
__global__ void __launch_bounds__(256) setup_w(const float* __restrict__ W, int sel) {
    __shared__ float tile[32][33];
    int kk = blockIdx.x * 32;
    int nn = blockIdx.y * 32;
    int txx = threadIdx.x & 31;
    int tyy = threadIdx.x >> 5;
#pragma unroll
    for (int j = 0; j < 4; j++) {
        int row = tyy * 4 + j;
        tile[row][txx] = W[(size_t)(kk + row) * G4 + nn + txx];
    }
    __syncthreads();
    __nv_bfloat16* dH = sel ? g_wxT_h : g_whT_h;
    __nv_bfloat16* dL = sel ? g_wxT_l : g_whT_l;
#pragma unroll
    for (int j = 0; j < 4; j++) {
        int row = tyy * 4 + j;
        float v = tile[txx][row];
        __nv_bfloat16 hi = __float2bfloat16(v);
        __nv_bfloat16 lo = __float2bfloat16(v - __bfloat162float(hi));
        size_t o = (size_t)(nn + row) * 1024 + kk + txx;
        dH[o] = hi;
        dL[o] = lo;
    }
}

// setup: h0 fp32 -> g_hbf buffer 0 (hi/lo split)
__global__ void __launch_bounds__(256) setup_h0(const float* __restrict__ h0) {
    int i = blockIdx.x * 256 + threadIdx.x;   // 0..65535
    float v = h0[i];
    __nv_bfloat16 hi = __float2bfloat16(v);
    __nv_bfloat16 lo = __float2bfloat16(v - __bfloat162float(hi));
    g_hbf_h[0][i] = hi;
    g_hbf_l[0][i] = lo;
}

// setup: x fp32 -> g_xbf hi/lo split
__global__ void __launch_bounds__(256) setup_x(const float* __restrict__ x) {
    size_t i = (size_t)blockIdx.x * 256 + threadIdx.x;
    float v = x[i];
    __nv_bfloat16 hi = __float2bfloat16(v);
    __nv_bfloat16 lo = __float2bfloat16(v - __bfloat162float(hi));
    g_xbf_h[i] = hi;
    g_xbf_l[i] = lo;
}

// ---------------------------------------------------------------------------
// smem layout shared by hmma_xw and lstm_persist (the PROVEN geometry)
// ---------------------------------------------------------------------------
#define RSTRB 1032
#define RSTRA 136
#define SB_H   0
#define SB_L   66048
#define SA     132096
#define ABYT   17408
#define SAT    201728
#define SMEM_TOTAL 211968

// ---------------------------------------------------------------------------
// xW HMMA GEMM using the persist-proven geometry.
// Block (hb-colblock, m-group): resident B = WxT slice (32 cols = 4 gates x 8 j,
// rows rg = gate*1024 + hb + j), loops over 8 m-subtiles of 64 x-rows.
// ---------------------------------------------------------------------------
__global__ void __launch_bounds__(256) hmma_xw(const float* __restrict__ bias) {
    extern __shared__ char smem[];
    uint32_t sbase = smem_u32(smem);
    float* At = (float*)(smem + SAT);     // [64][40]
    int tid = threadIdx.x;
    int wid = tid >> 5;
    int lane = tid & 31;
    int hb = blockIdx.x * 8;              // col block
    int mg = blockIdx.y;                  // m-group: rows [mg*512, mg*512+512)

    int wm = wid & 3;
    int wcg = wid >> 2;

    // ---- resident B (32 rows x 1024 k, hi+lo) — verbatim persist load, from WxT ----
    {
        int nl = tid >> 3;
        int seg = tid & 7;
        int rg = (nl >> 3) * 1024 + hb + (nl & 7);
        const uint4* srcH = (const uint4*)(g_wxT_h + (size_t)rg * Dd) + seg * 16;
        const uint4* srcL = (const uint4*)(g_wxT_l + (size_t)rg * Dd) + seg * 16;
        char* dH = smem + SB_H + nl * (RSTRB * 2) + seg * 256;
        char* dL = smem + SB_L + nl * (RSTRB * 2) + seg * 256;
#pragma unroll
        for (int i = 0; i < 16; i++) {
            ((uint4*)dH)[i] = srcH[i];
            ((uint4*)dL)[i] = srcL[i];
        }
    }
    __syncthreads();

    int lrow = lane & 7;
    int lk8  = (lane >> 4) * 8;
    int ln8  = ((lane >> 3) & 1) * 8;

    uint32_t laneA = ((uint32_t)(wm * 16 + ln8 + lrow) * RSTRA + lk8) * 2;
    uint32_t bLaneH = sbase + SB_H + ((uint32_t)(wcg * 16 + ln8 + lrow) * RSTRB + lk8) * 2;
    uint32_t bLaneL = bLaneH + (SB_L - SB_H);

    int srow = tid >> 2;                  // 0..63
    int sq = tid & 3;                     // 32-elem quarter
    uint32_t stH = sbase + SA + (uint32_t)(srow * (RSTRA * 2) + sq * 64);

    int en[2], ej[2];
#pragma unroll
    for (int it = 0; it < 2; it++) {
        int item = tid + it * 256;
        en[it] = item >> 3;
        ej[it] = item & 7;
    }
    float bv[2][4];
#pragma unroll
    for (int it = 0; it < 2; it++)
#pragma unroll
        for (int g = 0; g < 4; g++)
            bv[it][g] = __ldg(bias + g * 1024 + hb + ej[it]);

    for (int s = 0; s < 8; s++) {
        int m0 = (mg * 8 + s) * 64;
        const uint4* gH = (const uint4*)(g_xbf_h + (size_t)(m0 + srow) * Dd) + sq * 4;
        const uint4* gL = (const uint4*)(g_xbf_l + (size_t)(m0 + srow) * Dd) + sq * 4;

        // ---- stage chunk 0 via cp.async (verbatim persist) ----
        {
            uint32_t dH = stH;
            uint32_t dL = dH + ABYT;
#pragma unroll
            for (int i = 0; i < 4; i++) {
                CP_ASYNC16(dH + i * 16, gH + i);
                CP_ASYNC16(dL + i * 16, gL + i);
            }
            CP_COMMIT();
        }
        CP_WAIT0();
        __syncthreads();

        float acc[2][4];
#pragma unroll
        for (int nt = 0; nt < 2; nt++)
#pragma unroll
            for (int j = 0; j < 4; j++) acc[nt][j] = 0.0f;

        int p = 0;
        for (int c = 0; c < 8; c++) {
            if (c < 7) {
                const uint4* nH = gH + (c + 1) * 16;
                const uint4* nL = gL + (c + 1) * 16;
                uint32_t dH = stH + (uint32_t)((p ^ 1) * (2 * ABYT));
                uint32_t dL = dH + ABYT;
#pragma unroll
                for (int i = 0; i < 4; i++) {
                    CP_ASYNC16(dH + i * 16, nH + i);
                    CP_ASYNC16(dL + i * 16, nL + i);
                }
                CP_COMMIT();
            }

            uint32_t aH = sbase + SA + p * (2 * ABYT) + laneA;
            uint32_t aL = aH + ABYT;
            uint32_t bOff = (uint32_t)c * 256;
#pragma unroll
            for (int kc = 0; kc < 8; kc++) {
                uint32_t ko = kc * 32;
                uint32_t ah0, ah1, ah2, ah3, al0, al1, al2, al3;
                LDMX4(ah0, ah1, ah2, ah3, aH + ko);
                LDMX4(al0, al1, al2, al3, aL + ko);
                uint32_t r0, r1, r2, r3, s0, s1, s2, s3;
                LDMX4(r0, r1, r2, r3, bLaneH + bOff + ko);
                LDMX4(s0, s1, s2, s3, bLaneL + bOff + ko);

                MMA16816(acc[0][0], acc[0][1], acc[0][2], acc[0][3],
                         ah0, ah1, ah2, ah3, r0, r2);
                MMA16816(acc[1][0], acc[1][1], acc[1][2], acc[1][3],
                         ah0, ah1, ah2, ah3, r1, r3);
                MMA16816(acc[0][0], acc[0][1], acc[0][2], acc[0][3],
                         ah0, ah1, ah2, ah3, s0, s2);
                MMA16816(acc[1][0], acc[1][1], acc[1][2], acc[1][3],
                         ah0, ah1, ah2, ah3, s1, s3);
                MMA16816(acc[0][0], acc[0][1], acc[0][2], acc[0][3],
                         al0, al1, al2, al3, r0, r2);
                MMA16816(acc[1][0], acc[1][1], acc[1][2], acc[1][3],
                         al0, al1, al2, al3, r1, r3);
            }
            if (c < 7) CP_WAIT0();
            __syncthreads();
            p ^= 1;
        }

        // ---- stage accumulators into At[64][40] (verbatim persist) ----
        {
            int r = wm * 16 + (lane >> 2);
            int cb = wcg * 16 + 2 * (lane & 3);
#pragma unroll
            for (int nt = 0; nt < 2; nt++) {
                int cc = cb + nt * 8;
                At[r * 40 + cc]       = acc[nt][0];
                At[r * 40 + cc + 1]   = acc[nt][1];
                At[(r + 8) * 40 + cc]     = acc[nt][2];
                At[(r + 8) * 40 + cc + 1] = acc[nt][3];
            }
        }
        __syncthreads();

        // ---- write xW + bias (persist's en/ej/At read mapping) ----
#pragma unroll
        for (int it = 0; it < 2; it++) {
            int n = en[it], j = ej[it];
            float* gx = g_xw + (size_t)(m0 + n) * G4 + hb + j;
            gx[0]    = At[n * 40 + j]      + bv[it][0];
            gx[1024] = At[n * 40 + 8 + j]  + bv[it][1];
            gx[2048] = At[n * 40 + 16 + j] + bv[it][2];
            gx[3072] = At[n * 40 + 24 + j] + bv[it][3];
        }
    }
}

// ---------------------------------------------------------------------------
// Persistent LSTM — VERBATIM R10 (proven at 15.15 ms)
// ---------------------------------------------------------------------------
__global__ void __launch_bounds__(256) lstm_persist(float* __restrict__ out) {
    extern __shared__ char smem[];
    uint32_t sbase = smem_u32(smem);
    float* At = (float*)(smem + SAT);     // [64][40]
    int tid = threadIdx.x;
    int wid = tid >> 5;
    int lane = tid & 31;
    int bid = blockIdx.x;
    int hb = bid * 8;

    int wm = wid & 3;
    int wcg = wid >> 2;

    // ---- load resident B (32 rows x 1024 k, hi+lo) once ----
    {
        int nl = tid >> 3;
        int seg = tid & 7;
        int rg = (nl >> 3) * 1024 + hb + (nl & 7);
        const uint4* srcH = (const uint4*)(g_whT_h + (size_t)rg * Hh) + seg * 16;
        const uint4* srcL = (const uint4*)(g_whT_l + (size_t)rg * Hh) + seg * 16;
        char* dH = smem + SB_H + nl * (RSTRB * 2) + seg * 256;
        char* dL = smem + SB_L + nl * (RSTRB * 2) + seg * 256;
#pragma unroll
        for (int i = 0; i < 16; i++) {
            ((uint4*)dH)[i] = srcH[i];
            ((uint4*)dL)[i] = srcL[i];
        }
    }
    __syncthreads();

    int lrow = lane & 7;
    int lk8  = (lane >> 4) * 8;
    int ln8  = ((lane >> 3) & 1) * 8;

    uint32_t laneA = ((uint32_t)(wm * 16 + ln8 + lrow) * RSTRA + lk8) * 2;
    uint32_t bLaneH = sbase + SB_H + ((uint32_t)(wcg * 16 + ln8 + lrow) * RSTRB + lk8) * 2;
    uint32_t bLaneL = bLaneH + (SB_L - SB_H);

    int srow = tid >> 2;                  // 0..63
    int sq = tid & 3;                     // 32-elem quarter
    uint32_t stH = sbase + SA + (uint32_t)(srow * (RSTRA * 2) + sq * 64);

    float creg[2] = {0.0f, 0.0f};
    int en[2], ej[2];
#pragma unroll
    for (int it = 0; it < 2; it++) {
        int item = tid + it * 256;
        en[it] = item >> 3;
        ej[it] = item & 7;
    }

    for (int t = 0; t < Tt; t++) {
        // ---- prefetch epilogue xw operands (independent of h) ----
        float xwv[2][4];
#pragma unroll
        for (int it = 0; it < 2; it++) {
            const float* xw = g_xw + (size_t)(en[it] * Tt + t) * G4 + hb + ej[it];
            xwv[it][0] = __ldcg(xw);
            xwv[it][1] = __ldcg(xw + 1024);
            xwv[it][2] = __ldcg(xw + 2048);
            xwv[it][3] = __ldcg(xw + 3072);
        }

        int rb = t & 1;
        const __nv_bfloat16* hH = g_hbf_h[rb];
        const __nv_bfloat16* hL = g_hbf_l[rb];
        const uint4* gH = (const uint4*)(hH + (size_t)srow * Hh) + sq * 4;
        const uint4* gL = (const uint4*)(hL + (size_t)srow * Hh) + sq * 4;

        // ---- stage chunk 0 via cp.async (L2-only path) ----
        {
            uint32_t dH = stH;
            uint32_t dL = dH + ABYT;
#pragma unroll
            for (int i = 0; i < 4; i++) {
                CP_ASYNC16(dH + i * 16, gH + i);
                CP_ASYNC16(dL + i * 16, gL + i);
            }
            CP_COMMIT();
        }
        CP_WAIT0();
        __syncthreads();

        float acc[2][4];
#pragma unroll
        for (int nt = 0; nt < 2; nt++)
#pragma unroll
            for (int j = 0; j < 4; j++) acc[nt][j] = 0.0f;

        int p = 0;
        for (int c = 0; c < 8; c++) {
            if (c < 7) {
                const uint4* nH = gH + (c + 1) * 16;   // +128 elems = 16 uint4
                const uint4* nL = gL + (c + 1) * 16;
                uint32_t dH = stH + (uint32_t)((p ^ 1) * (2 * ABYT));
                uint32_t dL = dH + ABYT;
#pragma unroll
                for (int i = 0; i < 4; i++) {
                    CP_ASYNC16(dH + i * 16, nH + i);
                    CP_ASYNC16(dL + i * 16, nL + i);
                }
                CP_COMMIT();
            }

            uint32_t aH = sbase + SA + p * (2 * ABYT) + laneA;
            uint32_t aL = aH + ABYT;
            uint32_t bOff = (uint32_t)c * 256;
#pragma unroll
            for (int kc = 0; kc < 8; kc++) {
                uint32_t ko = kc * 32;
                uint32_t ah0, ah1, ah2, ah3, al0, al1, al2, al3;
                LDMX4(ah0, ah1, ah2, ah3, aH + ko);
                LDMX4(al0, al1, al2, al3, aL + ko);
                uint32_t r0, r1, r2, r3, s0, s1, s2, s3;
                LDMX4(r0, r1, r2, r3, bLaneH + bOff + ko);
                LDMX4(s0, s1, s2, s3, bLaneL + bOff + ko);

                MMA16816(acc[0][0], acc[0][1], acc[0][2], acc[0][3],
                         ah0, ah1, ah2, ah3, r0, r2);
                MMA16816(acc[1][0], acc[1][1], acc[1][2], acc[1][3],
                         ah0, ah1, ah2, ah3, r1, r3);
                MMA16816(acc[0][0], acc[0][1], acc[0][2], acc[0][3],
                         ah0, ah1, ah2, ah3, s0, s2);
                MMA16816(acc[1][0], acc[1][1], acc[1][2], acc[1][3],
                         ah0, ah1, ah2, ah3, s1, s3);
                MMA16816(acc[0][0], acc[0][1], acc[0][2], acc[0][3],
                         al0, al1, al2, al3, r0, r2);
                MMA16816(acc[1][0], acc[1][1], acc[1][2], acc[1][3],
                         al0, al1, al2, al3, r1, r3);
            }
            if (c < 7) CP_WAIT0();
            __syncthreads();
            p ^= 1;
        }

        // ---- stage accumulators into At[64][40] ----
        {
            int r = wm * 16 + (lane >> 2);
            int cb = wcg * 16 + 2 * (lane & 3);
#pragma unroll
            for (int nt = 0; nt < 2; nt++) {
                int cc = cb + nt * 8;
                At[r * 40 + cc]       = acc[nt][0];
                At[r * 40 + cc + 1]   = acc[nt][1];
                At[(r + 8) * 40 + cc]     = acc[nt][2];
                At[(r + 8) * 40 + cc + 1] = acc[nt][3];
            }
        }
        __syncthreads();

        // ---- block-local gates epilogue (2 items/thread) ----
        int wb = (t + 1) & 1;
#pragma unroll
        for (int it = 0; it < 2; it++) {
            int n = en[it], j = ej[it];

            float a0 = At[n * 40 + j]      + xwv[it][0];   // i
            float a1 = At[n * 40 + 8 + j]  + xwv[it][1];   // f
            float a2 = At[n * 40 + 16 + j] + xwv[it][2];   // o
            float a3 = At[n * 40 + 24 + j] + xwv[it][3];   // g

            float iv = fsigmoid(a0);
            float fv = fsigmoid(a1);
            float ov = fsigmoid(a2);
            float gv = ftanh(a3);

            float cn = fv * creg[it] + iv * gv;
            float hv = ov * ftanh(cn);
            creg[it] = cn;

            out[((size_t)n * Tt + t) * Hh + hb + j] = hv;

            __nv_bfloat16 hi = __float2bfloat16(hv);
            __nv_bfloat16 lo = __float2bfloat16(hv - __bfloat162float(hi));
            g_hbf_h[wb][n * Hh + hb + j] = hi;
            g_hbf_l[wb][n * Hh + hb + j] = lo;
        }

        grid_barrier();
    }
}

// ---------------------------------------------------------------------------
extern "C" void kernel_launch(void* const* d_in, const int* in_sizes, int n_in,
                              void* d_out, int out_size) {
    const float* x  = (const float*)d_in[0];   // [N,T,D]
    const float* h0 = (const float*)d_in[1];   // [N,H]
    const float* Wx = (const float*)d_in[2];   // [D,4H]
    const float* Wh = (const float*)d_in[3];   // [H,4H]
    const float* b  = (const float*)d_in[4];   // [4H]
    float* out = (float*)d_out;                // [N,T,H]

    dim3 gt(Dd / 32, G4 / 32);                 // (32,128)
    setup_w<<<gt, 256>>>(Wh, 0);
    setup_w<<<gt, 256>>>(Wx, 1);
    setup_h0<<<(Nn * Hh) / 256, 256>>>(h0);
    setup_x<<<(unsigned)(((size_t)Nn * Tt * Dd) / 256), 256>>>(x);

    cudaFuncSetAttribute(hmma_xw, cudaFuncAttributeMaxDynamicSharedMemorySize, SMEM_TOTAL);
    dim3 gx(128, 64);                          // col-blocks x m-groups
    hmma_xw<<<gx, 256, SMEM_TOTAL>>>(b);

    cudaFuncSetAttribute(lstm_persist, cudaFuncAttributeMaxDynamicSharedMemorySize, SMEM_TOTAL);
    lstm_persist<<<NBLK, 256, SMEM_TOTAL>>>(out);
}

// round 15
// speedup vs baseline: 1.5331x; 1.0415x over previous
#include <cuda_runtime.h>
#include <cuda_bf16.h>
#include <math.h>
#include <stdint.h>

#define Nn 64
#define Tt 512
#define Dd 1024
#define Hh 1024
#define G4 4096   // 4*Hh
#define NBLK 128  // persistent grid (co-resident on 148 SMs)

// ---------------- device scratch (allocation-free rule) ----------------
__device__ float g_xw[(size_t)Nn * Tt * G4];         // input projection [N*T,4H]
__device__ __nv_bfloat16 g_whT_h[(size_t)G4 * Hh];   // Wh^T hi  [4096 n][1024 k]
__device__ __nv_bfloat16 g_whT_l[(size_t)G4 * Hh];   // Wh^T lo
__device__ __nv_bfloat16 g_wxT_h[(size_t)G4 * Dd];   // Wx^T hi  [4096 n][1024 k]
__device__ __nv_bfloat16 g_wxT_l[(size_t)G4 * Dd];   // Wx^T lo
__device__ __nv_bfloat16 g_xbf_h[(size_t)Nn * Tt * Dd]; // x hi [32768 m][1024 k]
__device__ __nv_bfloat16 g_xbf_l[(size_t)Nn * Tt * Dd]; // x lo
__device__ __nv_bfloat16 g_hbf_h[2][Nn * Hh];        // h split hi, double-buffered
__device__ __nv_bfloat16 g_hbf_l[2][Nn * Hh];        // h split lo
__device__ unsigned g_count = 0;
__device__ unsigned g_gen = 0;

// ---------------- helpers ----------------
__device__ __forceinline__ uint32_t smem_u32(const void* p) {
    uint32_t a;
    asm("{ .reg .u64 t; cvta.to.shared.u64 t, %1; cvt.u32.u64 %0, t; }" : "=r"(a) : "l"(p));
    return a;
}

#define LDMX4(r0, r1, r2, r3, addr) \
    asm volatile("ldmatrix.sync.aligned.m8n8.x4.shared.b16 {%0,%1,%2,%3}, [%4];" \
                 : "=r"(r0), "=r"(r1), "=r"(r2), "=r"(r3) : "r"(addr))

#define MMA16816(c0, c1, c2, c3, a0, a1, a2, a3, b0, b1) \
    asm volatile("mma.sync.aligned.m16n8k16.row.col.f32.bf16.bf16.f32 " \
                 "{%0,%1,%2,%3}, {%4,%5,%6,%7}, {%8,%9}, {%0,%1,%2,%3};" \
                 : "+f"(c0), "+f"(c1), "+f"(c2), "+f"(c3) \
                 : "r"(a0), "r"(a1), "r"(a2), "r"(a3), "r"(b0), "r"(b1))

// cp.async: 16B global->shared, L2-only (.cg)
#define CP_ASYNC16(saddr, gptr) \
    asm volatile("cp.async.cg.shared.global [%0], [%1], 16;" :: "r"(saddr), "l"(gptr))
#define CP_COMMIT() asm volatile("cp.async.commit_group;" ::: "memory")
#define CP_WAIT0()  asm volatile("cp.async.wait_group 0;" ::: "memory")

// fast gates
__device__ __forceinline__ float fsigmoid(float x) {
    return __fdividef(1.0f, 1.0f + __expf(-x));
}
__device__ __forceinline__ float ftanh(float x) {
    float r;
    asm("tanh.approx.f32 %0, %1;" : "=f"(r) : "f"(x));
    return r;
}

// ---------------- grid barrier: atomic arrive, volatile poll ----------------
__device__ __forceinline__ void grid_barrier() {
    __syncthreads();
    if (threadIdx.x == 0) {
        __threadfence();
        unsigned gen = *(volatile unsigned*)&g_gen;
        if (atomicAdd(&g_count, 1u) == NBLK - 1) {
            atomicExch(&g_count, 0u);
            __threadfence();
            atomicAdd(&g_gen, 1u);
        } else {
            while (*(volatile unsigned*)&g_gen == gen) { }
        }
        __threadfence();
    }
    __syncthreads();
}

// ---------------------------------------------------------------------------
// setup: W [1024 k][4096 n] fp32 -> W^T hi/lo bf16 [4096 n][1024 k]
// sel = 0 -> g_whT, sel = 1 -> g_wxT.  (Globals referenced only in device code.)
// ---------------------------------------------------------------------------
__global__ void __launch_bounds__(256) setup_w(const float* __restrict__ W, int sel) {
    __shared__ float tile[32][33];
    int kk = blockIdx.x * 32;
    int nn = blockIdx.y * 32;
    int txx = threadIdx.x & 31;
    int tyy = threadIdx.x >> 5;
#pragma unroll
    for (int j = 0; j < 4; j++) {
        int row = tyy * 4 + j;
        tile[row][txx] = W[(size_t)(kk + row) * G4 + nn + txx];
    }
    __syncthreads();
    __nv_bfloat16* dH = sel ? g_wxT_h : g_whT_h;
    __nv_bfloat16* dL = sel ? g_wxT_l : g_whT_l;
#pragma unroll
    for (int j = 0; j < 4; j++) {
        int row = tyy * 4 + j;
        float v = tile[txx][row];
        __nv_bfloat16 hi = __float2bfloat16(v);
        __nv_bfloat16 lo = __float2bfloat16(v - __bfloat162float(hi));
        size_t o = (size_t)(nn + row) * 1024 + kk + txx;
        dH[o] = hi;
        dL[o] = lo;
    }
}

// setup: h0 fp32 -> g_hbf buffer 0 (hi/lo split)
__global__ void __launch_bounds__(256) setup_h0(const float* __restrict__ h0) {
    int i = blockIdx.x * 256 + threadIdx.x;   // 0..65535
    float v = h0[i];
    __nv_bfloat16 hi = __float2bfloat16(v);
    __nv_bfloat16 lo = __float2bfloat16(v - __bfloat162float(hi));
    g_hbf_h[0][i] = hi;
    g_hbf_l[0][i] = lo;
}

// setup: x fp32 -> g_xbf hi/lo split
__global__ void __launch_bounds__(256) setup_x(const float* __restrict__ x) {
    size_t i = (size_t)blockIdx.x * 256 + threadIdx.x;
    float v = x[i];
    __nv_bfloat16 hi = __float2bfloat16(v);
    __nv_bfloat16 lo = __float2bfloat16(v - __bfloat162float(hi));
    g_xbf_h[i] = hi;
    g_xbf_l[i] = lo;
}

// ---------------------------------------------------------------------------
// smem layout shared by hmma_xw and lstm_persist (the PROVEN geometry)
// ---------------------------------------------------------------------------
#define RSTRB 1032
#define RSTRA 136
#define SB_H   0
#define SB_L   66048
#define SA     132096
#define ABYT   17408
#define SAT    201728
#define SMEM_TOTAL 211968

// ---------------------------------------------------------------------------
// xW HMMA GEMM (persist-proven geometry) — VERBATIM R14 (passed, ~3.6 ms)
// ---------------------------------------------------------------------------
__global__ void __launch_bounds__(256) hmma_xw(const float* __restrict__ bias) {
    extern __shared__ char smem[];
    uint32_t sbase = smem_u32(smem);
    float* At = (float*)(smem + SAT);     // [64][40]
    int tid = threadIdx.x;
    int wid = tid >> 5;
    int lane = tid & 31;
    int hb = blockIdx.x * 8;              // col block
    int mg = blockIdx.y;                  // m-group: rows [mg*512, mg*512+512)

    int wm = wid & 3;
    int wcg = wid >> 2;

    {
        int nl = tid >> 3;
        int seg = tid & 7;
        int rg = (nl >> 3) * 1024 + hb + (nl & 7);
        const uint4* srcH = (const uint4*)(g_wxT_h + (size_t)rg * Dd) + seg * 16;
        const uint4* srcL = (const uint4*)(g_wxT_l + (size_t)rg * Dd) + seg * 16;
        char* dH = smem + SB_H + nl * (RSTRB * 2) + seg * 256;
        char* dL = smem + SB_L + nl * (RSTRB * 2) + seg * 256;
#pragma unroll
        for (int i = 0; i < 16; i++) {
            ((uint4*)dH)[i] = srcH[i];
            ((uint4*)dL)[i] = srcL[i];
        }
    }
    __syncthreads();

    int lrow = lane & 7;
    int lk8  = (lane >> 4) * 8;
    int ln8  = ((lane >> 3) & 1) * 8;

    uint32_t laneA = ((uint32_t)(wm * 16 + ln8 + lrow) * RSTRA + lk8) * 2;
    uint32_t bLaneH = sbase + SB_H + ((uint32_t)(wcg * 16 + ln8 + lrow) * RSTRB + lk8) * 2;
    uint32_t bLaneL = bLaneH + (SB_L - SB_H);

    int srow = tid >> 2;
    int sq = tid & 3;
    uint32_t stH = sbase + SA + (uint32_t)(srow * (RSTRA * 2) + sq * 64);

    int en[2], ej[2];
#pragma unroll
    for (int it = 0; it < 2; it++) {
        int item = tid + it * 256;
        en[it] = item >> 3;
        ej[it] = item & 7;
    }
    float bv[2][4];
#pragma unroll
    for (int it = 0; it < 2; it++)
#pragma unroll
        for (int g = 0; g < 4; g++)
            bv[it][g] = __ldg(bias + g * 1024 + hb + ej[it]);

    for (int s = 0; s < 8; s++) {
        int m0 = (mg * 8 + s) * 64;
        const uint4* gH = (const uint4*)(g_xbf_h + (size_t)(m0 + srow) * Dd) + sq * 4;
        const uint4* gL = (const uint4*)(g_xbf_l + (size_t)(m0 + srow) * Dd) + sq * 4;

        {
            uint32_t dH = stH;
            uint32_t dL = dH + ABYT;
#pragma unroll
            for (int i = 0; i < 4; i++) {
                CP_ASYNC16(dH + i * 16, gH + i);
                CP_ASYNC16(dL + i * 16, gL + i);
            }
            CP_COMMIT();
        }
        CP_WAIT0();
        __syncthreads();

        float acc[2][4];
#pragma unroll
        for (int nt = 0; nt < 2; nt++)
#pragma unroll
            for (int j = 0; j < 4; j++) acc[nt][j] = 0.0f;

        int p = 0;
        for (int c = 0; c < 8; c++) {
            if (c < 7) {
                const uint4* nH = gH + (c + 1) * 16;
                const uint4* nL = gL + (c + 1) * 16;
                uint32_t dH = stH + (uint32_t)((p ^ 1) * (2 * ABYT));
                uint32_t dL = dH + ABYT;
#pragma unroll
                for (int i = 0; i < 4; i++) {
                    CP_ASYNC16(dH + i * 16, nH + i);
                    CP_ASYNC16(dL + i * 16, nL + i);
                }
                CP_COMMIT();
            }

            uint32_t aH = sbase + SA + p * (2 * ABYT) + laneA;
            uint32_t aL = aH + ABYT;
            uint32_t bOff = (uint32_t)c * 256;
#pragma unroll
            for (int kc = 0; kc < 8; kc++) {
                uint32_t ko = kc * 32;
                uint32_t ah0, ah1, ah2, ah3, al0, al1, al2, al3;
                LDMX4(ah0, ah1, ah2, ah3, aH + ko);
                LDMX4(al0, al1, al2, al3, aL + ko);
                uint32_t r0, r1, r2, r3, s0, s1, s2, s3;
                LDMX4(r0, r1, r2, r3, bLaneH + bOff + ko);
                LDMX4(s0, s1, s2, s3, bLaneL + bOff + ko);

                MMA16816(acc[0][0], acc[0][1], acc[0][2], acc[0][3],
                         ah0, ah1, ah2, ah3, r0, r2);
                MMA16816(acc[1][0], acc[1][1], acc[1][2], acc[1][3],
                         ah0, ah1, ah2, ah3, r1, r3);
                MMA16816(acc[0][0], acc[0][1], acc[0][2], acc[0][3],
                         ah0, ah1, ah2, ah3, s0, s2);
                MMA16816(acc[1][0], acc[1][1], acc[1][2], acc[1][3],
                         ah0, ah1, ah2, ah3, s1, s3);
                MMA16816(acc[0][0], acc[0][1], acc[0][2], acc[0][3],
                         al0, al1, al2, al3, r0, r2);
                MMA16816(acc[1][0], acc[1][1], acc[1][2], acc[1][3],
                         al0, al1, al2, al3, r1, r3);
            }
            if (c < 7) CP_WAIT0();
            __syncthreads();
            p ^= 1;
        }

        {
            int r = wm * 16 + (lane >> 2);
            int cb = wcg * 16 + 2 * (lane & 3);
#pragma unroll
            for (int nt = 0; nt < 2; nt++) {
                int cc = cb + nt * 8;
                At[r * 40 + cc]       = acc[nt][0];
                At[r * 40 + cc + 1]   = acc[nt][1];
                At[(r + 8) * 40 + cc]     = acc[nt][2];
                At[(r + 8) * 40 + cc + 1] = acc[nt][3];
            }
        }
        __syncthreads();

#pragma unroll
        for (int it = 0; it < 2; it++) {
            int n = en[it], j = ej[it];
            float* gx = g_xw + (size_t)(m0 + n) * G4 + hb + j;
            gx[0]    = At[n * 40 + j]      + bv[it][0];
            gx[1024] = At[n * 40 + 8 + j]  + bv[it][1];
            gx[2048] = At[n * 40 + 16 + j] + bv[it][2];
            gx[3072] = At[n * 40 + 24 + j] + bv[it][3];
        }
    }
}

// ---------------------------------------------------------------------------
// Persistent LSTM — R14 structure + per-block ROTATED k-chunk order
// (chunk cc = (c + bid) & 7) to break L2 slice hot-spotting on the h broadcast.
// ---------------------------------------------------------------------------
__global__ void __launch_bounds__(256) lstm_persist(float* __restrict__ out) {
    extern __shared__ char smem[];
    uint32_t sbase = smem_u32(smem);
    float* At = (float*)(smem + SAT);     // [64][40]
    int tid = threadIdx.x;
    int wid = tid >> 5;
    int lane = tid & 31;
    int bid = blockIdx.x;
    int hb = bid * 8;
    int rot = bid & 7;                    // chunk rotation offset

    int wm = wid & 3;
    int wcg = wid >> 2;

    // ---- load resident B (32 rows x 1024 k, hi+lo) once ----
    {
        int nl = tid >> 3;
        int seg = tid & 7;
        int rg = (nl >> 3) * 1024 + hb + (nl & 7);
        const uint4* srcH = (const uint4*)(g_whT_h + (size_t)rg * Hh) + seg * 16;
        const uint4* srcL = (const uint4*)(g_whT_l + (size_t)rg * Hh) + seg * 16;
        char* dH = smem + SB_H + nl * (RSTRB * 2) + seg * 256;
        char* dL = smem + SB_L + nl * (RSTRB * 2) + seg * 256;
#pragma unroll
        for (int i = 0; i < 16; i++) {
            ((uint4*)dH)[i] = srcH[i];
            ((uint4*)dL)[i] = srcL[i];
        }
    }
    __syncthreads();

    int lrow = lane & 7;
    int lk8  = (lane >> 4) * 8;
    int ln8  = ((lane >> 3) & 1) * 8;

    uint32_t laneA = ((uint32_t)(wm * 16 + ln8 + lrow) * RSTRA + lk8) * 2;
    uint32_t bLaneH = sbase + SB_H + ((uint32_t)(wcg * 16 + ln8 + lrow) * RSTRB + lk8) * 2;
    uint32_t bLaneL = bLaneH + (SB_L - SB_H);

    int srow = tid >> 2;                  // 0..63
    int sq = tid & 3;                     // 32-elem quarter
    uint32_t stH = sbase + SA + (uint32_t)(srow * (RSTRA * 2) + sq * 64);

    float creg[2] = {0.0f, 0.0f};
    int en[2], ej[2];
#pragma unroll
    for (int it = 0; it < 2; it++) {
        int item = tid + it * 256;
        en[it] = item >> 3;
        ej[it] = item & 7;
    }

    for (int t = 0; t < Tt; t++) {
        // ---- prefetch epilogue xw operands (independent of h) ----
        float xwv[2][4];
#pragma unroll
        for (int it = 0; it < 2; it++) {
            const float* xw = g_xw + (size_t)(en[it] * Tt + t) * G4 + hb + ej[it];
            xwv[it][0] = __ldcg(xw);
            xwv[it][1] = __ldcg(xw + 1024);
            xwv[it][2] = __ldcg(xw + 2048);
            xwv[it][3] = __ldcg(xw + 3072);
        }

        int rb = t & 1;
        const __nv_bfloat16* hH = g_hbf_h[rb];
        const __nv_bfloat16* hL = g_hbf_l[rb];
        const uint4* gH = (const uint4*)(hH + (size_t)srow * Hh) + sq * 4;
        const uint4* gL = (const uint4*)(hL + (size_t)srow * Hh) + sq * 4;

        // ---- stage first (rotated) chunk via cp.async ----
        {
            int cc0 = rot;
            uint32_t dH = stH;
            uint32_t dL = dH + ABYT;
#pragma unroll
            for (int i = 0; i < 4; i++) {
                CP_ASYNC16(dH + i * 16, gH + cc0 * 16 + i);
                CP_ASYNC16(dL + i * 16, gL + cc0 * 16 + i);
            }
            CP_COMMIT();
        }
        CP_WAIT0();
        __syncthreads();

        float acc[2][4];
#pragma unroll
        for (int nt = 0; nt < 2; nt++)
#pragma unroll
            for (int j = 0; j < 4; j++) acc[nt][j] = 0.0f;

        int p = 0;
        for (int c = 0; c < 8; c++) {
            int cc = (c + rot) & 7;       // chunk this iteration computes
            if (c < 7) {
                int pc = (c + 1 + rot) & 7;   // chunk to prefetch
                const uint4* nH = gH + pc * 16;
                const uint4* nL = gL + pc * 16;
                uint32_t dH = stH + (uint32_t)((p ^ 1) * (2 * ABYT));
                uint32_t dL = dH + ABYT;
#pragma unroll
                for (int i = 0; i < 4; i++) {
                    CP_ASYNC16(dH + i * 16, nH + i);
                    CP_ASYNC16(dL + i * 16, nL + i);
                }
                CP_COMMIT();
            }

            uint32_t aH = sbase + SA + p * (2 * ABYT) + laneA;
            uint32_t aL = aH + ABYT;
            uint32_t bOff = (uint32_t)cc * 256;
#pragma unroll
            for (int kc = 0; kc < 8; kc++) {
                uint32_t ko = kc * 32;
                uint32_t ah0, ah1, ah2, ah3, al0, al1, al2, al3;
                LDMX4(ah0, ah1, ah2, ah3, aH + ko);
                LDMX4(al0, al1, al2, al3, aL + ko);
                uint32_t r0, r1, r2, r3, s0, s1, s2, s3;
                LDMX4(r0, r1, r2, r3, bLaneH + bOff + ko);
                LDMX4(s0, s1, s2, s3, bLaneL + bOff + ko);

                MMA16816(acc[0][0], acc[0][1], acc[0][2], acc[0][3],
                         ah0, ah1, ah2, ah3, r0, r2);
                MMA16816(acc[1][0], acc[1][1], acc[1][2], acc[1][3],
                         ah0, ah1, ah2, ah3, r1, r3);
                MMA16816(acc[0][0], acc[0][1], acc[0][2], acc[0][3],
                         ah0, ah1, ah2, ah3, s0, s2);
                MMA16816(acc[1][0], acc[1][1], acc[1][2], acc[1][3],
                         ah0, ah1, ah2, ah3, s1, s3);
                MMA16816(acc[0][0], acc[0][1], acc[0][2], acc[0][3],
                         al0, al1, al2, al3, r0, r2);
                MMA16816(acc[1][0], acc[1][1], acc[1][2], acc[1][3],
                         al0, al1, al2, al3, r1, r3);
            }
            if (c < 7) CP_WAIT0();
            __syncthreads();
            p ^= 1;
        }

        // ---- stage accumulators into At[64][40] ----
        {
            int r = wm * 16 + (lane >> 2);
            int cb = wcg * 16 + 2 * (lane & 3);
#pragma unroll
            for (int nt = 0; nt < 2; nt++) {
                int cc = cb + nt * 8;
                At[r * 40 + cc]       = acc[nt][0];
                At[r * 40 + cc + 1]   = acc[nt][1];
                At[(r + 8) * 40 + cc]     = acc[nt][2];
                At[(r + 8) * 40 + cc + 1] = acc[nt][3];
            }
        }
        __syncthreads();

        // ---- block-local gates epilogue (2 items/thread) ----
        int wb = (t + 1) & 1;
#pragma unroll
        for (int it = 0; it < 2; it++) {
            int n = en[it], j = ej[it];

            float a0 = At[n * 40 + j]      + xwv[it][0];   // i
            float a1 = At[n * 40 + 8 + j]  + xwv[it][1];   // f
            float a2 = At[n * 40 + 16 + j] + xwv[it][2];   // o
            float a3 = At[n * 40 + 24 + j] + xwv[it][3];   // g

            float iv = fsigmoid(a0);
            float fv = fsigmoid(a1);
            float ov = fsigmoid(a2);
            float gv = ftanh(a3);

            float cn = fv * creg[it] + iv * gv;
            float hv = ov * ftanh(cn);
            creg[it] = cn;

            out[((size_t)n * Tt + t) * Hh + hb + j] = hv;

            __nv_bfloat16 hi = __float2bfloat16(hv);
            __nv_bfloat16 lo = __float2bfloat16(hv - __bfloat162float(hi));
            g_hbf_h[wb][n * Hh + hb + j] = hi;
            g_hbf_l[wb][n * Hh + hb + j] = lo;
        }

        grid_barrier();
    }
}

// ---------------------------------------------------------------------------
extern "C" void kernel_launch(void* const* d_in, const int* in_sizes, int n_in,
                              void* d_out, int out_size) {
    const float* x  = (const float*)d_in[0];   // [N,T,D]
    const float* h0 = (const float*)d_in[1];   // [N,H]
    const float* Wx = (const float*)d_in[2];   // [D,4H]
    const float* Wh = (const float*)d_in[3];   // [H,4H]
    const float* b  = (const float*)d_in[4];   // [4H]
    float* out = (float*)d_out;                // [N,T,H]

    dim3 gt(Dd / 32, G4 / 32);                 // (32,128)
    setup_w<<<gt, 256>>>(Wh, 0);
    setup_w<<<gt, 256>>>(Wx, 1);
    setup_h0<<<(Nn * Hh) / 256, 256>>>(h0);
    setup_x<<<(unsigned)(((size_t)Nn * Tt * Dd) / 256), 256>>>(x);

    cudaFuncSetAttribute(hmma_xw, cudaFuncAttributeMaxDynamicSharedMemorySize, SMEM_TOTAL);
    dim3 gx(128, 64);                          // col-blocks x m-groups
    hmma_xw<<<gx, 256, SMEM_TOTAL>>>(b);

    cudaFuncSetAttribute(lstm_persist, cudaFuncAttributeMaxDynamicSharedMemorySize, SMEM_TOTAL);
    lstm_persist<<<NBLK, 256, SMEM_TOTAL>>>(out);
}